// round 1
// baseline (speedup 1.0000x reference)
#include <cuda_runtime.h>
#include <math.h>

#define EMB    64
#define NHEAD  4
#define HEADD  16
#define BB     8
#define SS     2048
#define NTOK   (BB*SS)            // 16384
#define EPS    1e-5f
#define SCALE  0.25f

#define TQ     128                // queries per attention block (1 per thread)
#define TK     16                 // keys per chunk
#define NCHUNK (SS/TK)            // 128

// ---------------- device scratch (no allocations allowed) ----------------
__device__ float g_Q[NTOK*EMB];      // [b][h][s][16]
__device__ float g_K[NTOK*EMB];
__device__ float g_V[NTOK*EMB];
__device__ float g_heads[NTOK*EMB];  // concat layout [b][s][h*16+k]

__device__ __forceinline__ float warp_sum(float v) {
#pragma unroll
    for (int o = 16; o > 0; o >>= 1) v += __shfl_xor_sync(0xffffffffu, v, o);
    return v;
}

// =====================================================================
// Kernel 1: QKV projection.  warp-per-token, weights in shared (48KB).
// q[b,h,s,k] = sum_d x[d] * Wq[h,d,k]   (SCALE folded into Wq)
// =====================================================================
__global__ void __launch_bounds__(256) qkv_kernel(
    const float* __restrict__ data,
    const float* __restrict__ Wq,
    const float* __restrict__ Wk,
    const float* __restrict__ Wv)
{
    __shared__ float Wqs[4096];   // [d][c], c = h*16+k
    __shared__ float Wks[4096];
    __shared__ float Wvs[4096];

    const int tid = threadIdx.x;
    for (int i = tid; i < 4096; i += 256) {
        int d = i >> 6, c = i & 63;
        int h = c >> 4, k = c & 15;
        int src = h * (EMB * HEADD) + d * HEADD + k;
        Wqs[i] = Wq[src] * SCALE;
        Wks[i] = Wk[src];
        Wvs[i] = Wv[src];
    }
    __syncthreads();

    const int w    = tid >> 5;
    const int lane = tid & 31;
    const int tpw  = NTOK / (gridDim.x * 8);
    const int tok0 = (blockIdx.x * 8 + w) * tpw;

    for (int t = 0; t < tpw; t++) {
        const int tok = tok0 + t;
        const float x0 = data[tok * 64 + lane];
        const float x1 = data[tok * 64 + lane + 32];

        float q0 = 0.f, q1 = 0.f, k0 = 0.f, k1 = 0.f, v0 = 0.f, v1 = 0.f;
#pragma unroll
        for (int d = 0; d < 32; d++) {
            const float xv = __shfl_sync(0xffffffffu, x0, d);
            q0 = fmaf(xv, Wqs[d * 64 + lane],      q0);
            q1 = fmaf(xv, Wqs[d * 64 + lane + 32], q1);
            k0 = fmaf(xv, Wks[d * 64 + lane],      k0);
            k1 = fmaf(xv, Wks[d * 64 + lane + 32], k1);
            v0 = fmaf(xv, Wvs[d * 64 + lane],      v0);
            v1 = fmaf(xv, Wvs[d * 64 + lane + 32], v1);
        }
#pragma unroll
        for (int d = 32; d < 64; d++) {
            const float xv = __shfl_sync(0xffffffffu, x1, d - 32);
            q0 = fmaf(xv, Wqs[d * 64 + lane],      q0);
            q1 = fmaf(xv, Wqs[d * 64 + lane + 32], q1);
            k0 = fmaf(xv, Wks[d * 64 + lane],      k0);
            k1 = fmaf(xv, Wks[d * 64 + lane + 32], k1);
            v0 = fmaf(xv, Wvs[d * 64 + lane],      v0);
            v1 = fmaf(xv, Wvs[d * 64 + lane + 32], v1);
        }

        const int b  = tok >> 11;          // tok / 2048
        const int s  = tok & 2047;
        const int h0 = lane >> 4;          // c = lane        -> head h0
        const int kk = lane & 15;          //                 -> dim kk
        // c = lane+32 -> head h0+2, same kk
        const int a0 = ((b * NHEAD + h0)     * SS + s) * HEADD + kk;
        const int a1 = ((b * NHEAD + h0 + 2) * SS + s) * HEADD + kk;
        g_Q[a0] = q0; g_Q[a1] = q1;
        g_K[a0] = k0; g_K[a1] = k1;
        g_V[a0] = v0; g_V[a1] = v1;
    }
}

// =====================================================================
// Kernel 2: flash attention. 1 thread = 1 query row. K/V streamed in
// 16-key chunks through double-buffered shared; all LDS are broadcasts.
// =====================================================================
__global__ void __launch_bounds__(128) attn_kernel()
{
    __shared__ float4 Ksh[2][TK * 4];   // 16 rows x 16 floats, per buffer
    __shared__ float4 Vsh[2][TK * 4];

    const int bh  = blockIdx.x;                 // 0..31
    const int tid = threadIdx.x;
    const int s   = blockIdx.y * TQ + tid;      // query index in [0, S)

    const float* Qp = g_Q + ((size_t)bh * SS + s) * HEADD;
    const float4 q0 = ((const float4*)Qp)[0];
    const float4 q1 = ((const float4*)Qp)[1];
    const float4 q2 = ((const float4*)Qp)[2];
    const float4 q3 = ((const float4*)Qp)[3];

    float4 o0 = make_float4(0.f, 0.f, 0.f, 0.f);
    float4 o1 = o0, o2 = o0, o3 = o0;
    float m = -1e30f, l = 0.f;

    const float4* Kg = (const float4*)(g_K + (size_t)bh * SS * HEADD);
    const float4* Vg = (const float4*)(g_V + (size_t)bh * SS * HEADD);

    // chunk = 16 rows x 16 floats = 64 float4; threads 0..63 load K, 64..127 load V
    const int role = tid >> 6;
    const int idx  = tid & 63;
    const float4* srcp = role ? Vg : Kg;
    float4* dstA = role ? &Vsh[0][0] : &Ksh[0][0];
    float4* dstB = role ? &Vsh[1][0] : &Ksh[1][0];

    float4 nxt = srcp[idx];
    dstA[idx] = nxt;
    __syncthreads();

    for (int c = 0; c < NCHUNK; c++) {
        const int buf = c & 1;
        if (c + 1 < NCHUNK) nxt = srcp[(c + 1) * 64 + idx];   // prefetch

        // ---- scores: 16 keys x dot16 ----
        float sc[TK];
#pragma unroll
        for (int j = 0; j < TK; j++) {
            const float4* kr = &Ksh[buf][j * 4];
            const float4 k0 = kr[0], k1 = kr[1], k2 = kr[2], k3 = kr[3];
            float d;
            d = q0.x * k0.x;
            d = fmaf(q0.y, k0.y, d); d = fmaf(q0.z, k0.z, d); d = fmaf(q0.w, k0.w, d);
            d = fmaf(q1.x, k1.x, d); d = fmaf(q1.y, k1.y, d);
            d = fmaf(q1.z, k1.z, d); d = fmaf(q1.w, k1.w, d);
            d = fmaf(q2.x, k2.x, d); d = fmaf(q2.y, k2.y, d);
            d = fmaf(q2.z, k2.z, d); d = fmaf(q2.w, k2.w, d);
            d = fmaf(q3.x, k3.x, d); d = fmaf(q3.y, k3.y, d);
            d = fmaf(q3.z, k3.z, d); d = fmaf(q3.w, k3.w, d);
            sc[j] = d;
        }

        // ---- online softmax ----
        float mt = sc[0];
#pragma unroll
        for (int j = 1; j < TK; j++) mt = fmaxf(mt, sc[j]);
        const float mnew  = fmaxf(m, mt);
        const float alpha = __expf(m - mnew);
        float psum = 0.f;
#pragma unroll
        for (int j = 0; j < TK; j++) { sc[j] = __expf(sc[j] - mnew); psum += sc[j]; }
        l = l * alpha + psum;
        m = mnew;

        o0.x *= alpha; o0.y *= alpha; o0.z *= alpha; o0.w *= alpha;
        o1.x *= alpha; o1.y *= alpha; o1.z *= alpha; o1.w *= alpha;
        o2.x *= alpha; o2.y *= alpha; o2.z *= alpha; o2.w *= alpha;
        o3.x *= alpha; o3.y *= alpha; o3.z *= alpha; o3.w *= alpha;

        // ---- P @ V ----
#pragma unroll
        for (int j = 0; j < TK; j++) {
            const float4* vr = &Vsh[buf][j * 4];
            const float p = sc[j];
            const float4 v0 = vr[0], v1 = vr[1], v2 = vr[2], v3 = vr[3];
            o0.x = fmaf(p, v0.x, o0.x); o0.y = fmaf(p, v0.y, o0.y);
            o0.z = fmaf(p, v0.z, o0.z); o0.w = fmaf(p, v0.w, o0.w);
            o1.x = fmaf(p, v1.x, o1.x); o1.y = fmaf(p, v1.y, o1.y);
            o1.z = fmaf(p, v1.z, o1.z); o1.w = fmaf(p, v1.w, o1.w);
            o2.x = fmaf(p, v2.x, o2.x); o2.y = fmaf(p, v2.y, o2.y);
            o2.z = fmaf(p, v2.z, o2.z); o2.w = fmaf(p, v2.w, o2.w);
            o3.x = fmaf(p, v3.x, o3.x); o3.y = fmaf(p, v3.y, o3.y);
            o3.z = fmaf(p, v3.z, o3.z); o3.w = fmaf(p, v3.w, o3.w);
        }

        __syncthreads();                 // everyone done reading buf^1's future slot
        if (c + 1 < NCHUNK) {
            float4* dst = (buf ? dstA : dstB);
            dst[idx] = nxt;
        }
        __syncthreads();
    }

    const float inv = 1.f / l;
    o0.x *= inv; o0.y *= inv; o0.z *= inv; o0.w *= inv;
    o1.x *= inv; o1.y *= inv; o1.z *= inv; o1.w *= inv;
    o2.x *= inv; o2.y *= inv; o2.z *= inv; o2.w *= inv;
    o3.x *= inv; o3.y *= inv; o3.z *= inv; o3.w *= inv;

    const int b = bh >> 2, h = bh & 3;
    float4* op = (float4*)(g_heads + ((size_t)(b * SS + s)) * EMB + h * HEADD);
    op[0] = o0; op[1] = o1; op[2] = o2; op[3] = o3;
}

// =====================================================================
// Kernel 3: Wo proj + residual + LN1 + FFN(relu) + residual + LN2.
// warp-per-token; weights (48KB) in shared; biases/LN params in regs.
// =====================================================================
__global__ void __launch_bounds__(256) post_kernel(
    const float* __restrict__ data,
    const float* __restrict__ Wo,  const float* __restrict__ bo,
    const float* __restrict__ g1,  const float* __restrict__ bl1,
    const float* __restrict__ W1,  const float* __restrict__ b1,
    const float* __restrict__ W2,  const float* __restrict__ b2,
    const float* __restrict__ g2,  const float* __restrict__ bl2,
    float* __restrict__ out)
{
    __shared__ float Wos[4096];
    __shared__ float W1s[4096];
    __shared__ float W2s[4096];

    const int tid = threadIdx.x;
    for (int i = tid; i < 4096; i += 256) {
        Wos[i] = Wo[i]; W1s[i] = W1[i]; W2s[i] = W2[i];
    }
    __syncthreads();

    const int w    = tid >> 5;
    const int lane = tid & 31;

    // per-lane parameters (indexed only by output column)
    const float bo0 = bo[lane],  bo1 = bo[lane + 32];
    const float b10 = b1[lane],  b11 = b1[lane + 32];
    const float b20 = b2[lane],  b21 = b2[lane + 32];
    const float g10 = g1[lane],  g11 = g1[lane + 32];
    const float e10 = bl1[lane], e11 = bl1[lane + 32];
    const float g20 = g2[lane],  g21 = g2[lane + 32];
    const float e20 = bl2[lane], e21 = bl2[lane + 32];

    const int tpw  = NTOK / (gridDim.x * 8);
    const int tok0 = (blockIdx.x * 8 + w) * tpw;

    for (int t = 0; t < tpw; t++) {
        const int tok = tok0 + t;
        // attention output (concat layout)
        const float a0 = g_heads[tok * 64 + lane];
        const float a1 = g_heads[tok * 64 + lane + 32];

        // attn_out = a @ Wo + bo
        float acc0 = bo0, acc1 = bo1;
#pragma unroll
        for (int d = 0; d < 32; d++) {
            const float xv = __shfl_sync(0xffffffffu, a0, d);
            acc0 = fmaf(xv, Wos[d * 64 + lane],      acc0);
            acc1 = fmaf(xv, Wos[d * 64 + lane + 32], acc1);
        }
#pragma unroll
        for (int d = 32; d < 64; d++) {
            const float xv = __shfl_sync(0xffffffffu, a1, d - 32);
            acc0 = fmaf(xv, Wos[d * 64 + lane],      acc0);
            acc1 = fmaf(xv, Wos[d * 64 + lane + 32], acc1);
        }

        float r0 = data[tok * 64 + lane]      + acc0;
        float r1 = data[tok * 64 + lane + 32] + acc1;

        // LN1
        float mean = warp_sum(r0 + r1) * (1.f / 64.f);
        float d0 = r0 - mean, d1 = r1 - mean;
        float var = warp_sum(d0 * d0 + d1 * d1) * (1.f / 64.f);
        float inv = rsqrtf(var + EPS);
        const float x10 = d0 * inv * g10 + e10;
        const float x11 = d1 * inv * g11 + e11;

        // h = relu(x1 @ W1 + b1)
        acc0 = b10; acc1 = b11;
#pragma unroll
        for (int d = 0; d < 32; d++) {
            const float xv = __shfl_sync(0xffffffffu, x10, d);
            acc0 = fmaf(xv, W1s[d * 64 + lane],      acc0);
            acc1 = fmaf(xv, W1s[d * 64 + lane + 32], acc1);
        }
#pragma unroll
        for (int d = 32; d < 64; d++) {
            const float xv = __shfl_sync(0xffffffffu, x11, d - 32);
            acc0 = fmaf(xv, W1s[d * 64 + lane],      acc0);
            acc1 = fmaf(xv, W1s[d * 64 + lane + 32], acc1);
        }
        const float h0 = fmaxf(acc0, 0.f);
        const float h1 = fmaxf(acc1, 0.f);

        // ff = h @ W2 + b2
        acc0 = b20; acc1 = b21;
#pragma unroll
        for (int d = 0; d < 32; d++) {
            const float xv = __shfl_sync(0xffffffffu, h0, d);
            acc0 = fmaf(xv, W2s[d * 64 + lane],      acc0);
            acc1 = fmaf(xv, W2s[d * 64 + lane + 32], acc1);
        }
#pragma unroll
        for (int d = 32; d < 64; d++) {
            const float xv = __shfl_sync(0xffffffffu, h1, d - 32);
            acc0 = fmaf(xv, W2s[d * 64 + lane],      acc0);
            acc1 = fmaf(xv, W2s[d * 64 + lane + 32], acc1);
        }

        r0 = acc0 + x10;
        r1 = acc1 + x11;

        // LN2
        mean = warp_sum(r0 + r1) * (1.f / 64.f);
        d0 = r0 - mean; d1 = r1 - mean;
        var = warp_sum(d0 * d0 + d1 * d1) * (1.f / 64.f);
        inv = rsqrtf(var + EPS);

        out[tok * 64 + lane]      = d0 * inv * g20 + e20;
        out[tok * 64 + lane + 32] = d1 * inv * g21 + e21;
    }
}

// =====================================================================
extern "C" void kernel_launch(void* const* d_in, const int* in_sizes, int n_in,
                              void* d_out, int out_size)
{
    const float* data  = (const float*)d_in[0];
    const float* Wq    = (const float*)d_in[1];
    const float* Wk    = (const float*)d_in[2];
    const float* Wv    = (const float*)d_in[3];
    const float* Wo    = (const float*)d_in[4];
    const float* bo    = (const float*)d_in[5];
    const float* ln1_g = (const float*)d_in[6];
    const float* ln1_b = (const float*)d_in[7];
    const float* W1    = (const float*)d_in[8];
    const float* b1    = (const float*)d_in[9];
    const float* W2    = (const float*)d_in[10];
    const float* b2    = (const float*)d_in[11];
    const float* ln2_g = (const float*)d_in[12];
    const float* ln2_b = (const float*)d_in[13];
    float* out = (float*)d_out;

    qkv_kernel<<<256, 256>>>(data, Wq, Wk, Wv);
    attn_kernel<<<dim3(NHEAD * BB, SS / TQ), 128>>>();
    post_kernel<<<256, 256>>>(data, Wo, bo, ln1_g, ln1_b, W1, b1,
                              W2, b2, ln2_g, ln2_b, out);
}

// round 5
// speedup vs baseline: 2.7240x; 2.7240x over previous
#include <cuda_runtime.h>
#include <cuda_fp16.h>
#include <math.h>

#define EMB    64
#define NHEAD  4
#define HEADD  16
#define BB     8
#define SS     2048
#define NTOK   (BB*SS)            // 16384
#define EPS    1e-5f
// exp2-domain scale: 1/sqrt(16) * log2(e)
#define QSCALE (0.25f * 1.44269504088896f)

#define BK     64                 // keys per chunk
#define NCH    (SS/BK)            // 32

// ---------------- device scratch (no allocations allowed) ----------------
// per-head layouts: [bh][s][16] with bh in [0, BB*NHEAD) -> NTOK*EMB halves total
__device__ __align__(16) __half g_Qh[NTOK*EMB];   // [bh][s][16], QSCALE folded in
__device__ __align__(16) __half g_Kh[NTOK*EMB];   // [bh][s][16]
__device__ __align__(16) __half g_Vt[NTOK*EMB];   // [bh][16][s]  (transposed!)
__device__ __align__(16) float  g_heads[NTOK*EMB];  // concat layout [b][s][h*16+k]

__device__ __forceinline__ float warp_sum(float v) {
#pragma unroll
    for (int o = 16; o > 0; o >>= 1) v += __shfl_xor_sync(0xffffffffu, v, o);
    return v;
}

__device__ __forceinline__ void mma_16816(float* d, const unsigned* a,
                                          unsigned b0, unsigned b1) {
    asm volatile(
        "mma.sync.aligned.m16n8k16.row.col.f32.f16.f16.f32 "
        "{%0,%1,%2,%3}, {%4,%5,%6,%7}, {%8,%9}, {%0,%1,%2,%3};\n"
        : "+f"(d[0]), "+f"(d[1]), "+f"(d[2]), "+f"(d[3])
        : "r"(a[0]), "r"(a[1]), "r"(a[2]), "r"(a[3]), "r"(b0), "r"(b1));
}

// =====================================================================
// Kernel 1: QKV projection -> fp16 outputs. warp-per-token.
// =====================================================================
__global__ void __launch_bounds__(256) qkv_kernel(
    const float* __restrict__ data,
    const float* __restrict__ Wq,
    const float* __restrict__ Wk,
    const float* __restrict__ Wv)
{
    __shared__ float Wqs[4096];   // [d][c], c = h*16+k
    __shared__ float Wks[4096];
    __shared__ float Wvs[4096];

    const int tid = threadIdx.x;
    for (int i = tid; i < 4096; i += 256) {
        int d = i >> 6, c = i & 63;
        int h = c >> 4, k = c & 15;
        int src = h * (EMB * HEADD) + d * HEADD + k;
        Wqs[i] = Wq[src] * QSCALE;
        Wks[i] = Wk[src];
        Wvs[i] = Wv[src];
    }
    __syncthreads();

    const int w    = tid >> 5;
    const int lane = tid & 31;
    const int tpw  = NTOK / (gridDim.x * 8);
    const int tok0 = (blockIdx.x * 8 + w) * tpw;

    for (int t = 0; t < tpw; t++) {
        const int tok = tok0 + t;
        const float x0 = data[tok * 64 + lane];
        const float x1 = data[tok * 64 + lane + 32];

        float q0 = 0.f, q1 = 0.f, k0 = 0.f, k1 = 0.f, v0 = 0.f, v1 = 0.f;
#pragma unroll
        for (int d = 0; d < 32; d++) {
            const float xv = __shfl_sync(0xffffffffu, x0, d);
            q0 = fmaf(xv, Wqs[d * 64 + lane],      q0);
            q1 = fmaf(xv, Wqs[d * 64 + lane + 32], q1);
            k0 = fmaf(xv, Wks[d * 64 + lane],      k0);
            k1 = fmaf(xv, Wks[d * 64 + lane + 32], k1);
            v0 = fmaf(xv, Wvs[d * 64 + lane],      v0);
            v1 = fmaf(xv, Wvs[d * 64 + lane + 32], v1);
        }
#pragma unroll
        for (int d = 32; d < 64; d++) {
            const float xv = __shfl_sync(0xffffffffu, x1, d - 32);
            q0 = fmaf(xv, Wqs[d * 64 + lane],      q0);
            q1 = fmaf(xv, Wqs[d * 64 + lane + 32], q1);
            k0 = fmaf(xv, Wks[d * 64 + lane],      k0);
            k1 = fmaf(xv, Wks[d * 64 + lane + 32], k1);
            v0 = fmaf(xv, Wvs[d * 64 + lane],      v0);
            v1 = fmaf(xv, Wvs[d * 64 + lane + 32], v1);
        }

        const int b  = tok >> 11;
        const int s  = tok & 2047;
        const int h0 = lane >> 4;
        const int kk = lane & 15;
        const int bh0 = b * NHEAD + h0;
        const int bh1 = bh0 + 2;
        const int a0 = (bh0 * SS + s) * HEADD + kk;
        const int a1 = (bh1 * SS + s) * HEADD + kk;
        g_Qh[a0] = __float2half_rn(q0); g_Qh[a1] = __float2half_rn(q1);
        g_Kh[a0] = __float2half_rn(k0); g_Kh[a1] = __float2half_rn(k1);
        // V transposed: [bh][kk][s]
        g_Vt[((size_t)bh0 * HEADD + kk) * SS + s] = __float2half_rn(v0);
        g_Vt[((size_t)bh1 * HEADD + kk) * SS + s] = __float2half_rn(v1);
    }
}

// =====================================================================
// Kernel 2: fp16 tensor-core flash attention (no-max softmax).
// Block: 128 threads (4 warps), 128 query rows; warp = 32 rows.
// Per chunk: S = Q@K^T (mma), P = exp2(S) in fp16, O += P@[V | 1 0..]
// =====================================================================
__global__ void __launch_bounds__(128) attn_kernel()
{
    __shared__ __align__(16) __half Ksh[2][BK][24];   // stride 24 halves (48B)
    __shared__ __align__(16) __half Vts[2][24][72];   // [dim(+l cols)][key]

    const int bh   = blockIdx.x;
    const int tid  = threadIdx.x;
    const int warp = tid >> 5;
    const int lane = tid & 31;
    const int gr   = lane >> 2;   // 0..7
    const int gc   = lane & 3;    // 0..3
    const int qrow0 = blockIdx.y * 128 + warp * 32;

    // constant rows 16..23 of Vt tiles: dim16 = ones (row-sum column), rest 0
    for (int i = tid; i < 2 * 8 * 72; i += 128) {
        int bufi = i / (8 * 72);
        int rem  = i % (8 * 72);
        int r = rem / 72, cc = rem % 72;
        Vts[bufi][16 + r][cc] = __float2half(r == 0 ? 1.0f : 0.0f);
    }

    // Q fragments (held for whole kernel)
    const __half* Qbh = g_Qh + (size_t)bh * SS * HEADD;
    unsigned qa[2][4];
#pragma unroll
    for (int mt = 0; mt < 2; mt++) {
        const __half* r0 = Qbh + (size_t)(qrow0 + mt * 16 + gr) * HEADD;
        qa[mt][0] = *(const unsigned*)(r0 + 2 * gc);
        qa[mt][1] = *(const unsigned*)(r0 + 8 * HEADD + 2 * gc);
        qa[mt][2] = *(const unsigned*)(r0 + 2 * gc + 8);
        qa[mt][3] = *(const unsigned*)(r0 + 8 * HEADD + 2 * gc + 8);
    }

    const __half* Kbh = g_Kh + (size_t)bh * SS * HEADD;
    const __half* Vbh = g_Vt + (size_t)bh * HEADD * SS;

    const int kr = tid >> 1, ko = (tid & 1) * 8;   // K: row, half-offset
    const int vd = tid >> 3, vo = (tid & 7) * 8;   // V: dim, key-offset

    float4 nk = *(const float4*)(Kbh + (size_t)kr * HEADD + ko);
    float4 nv = *(const float4*)(Vbh + (size_t)vd * SS + vo);
    *(float4*)&Ksh[0][kr][ko] = nk;
    *(float4*)&Vts[0][vd][vo] = nv;
    __syncthreads();

    float O[2][3][4] = {};    // [mt][nv-tile][frag]; nv=2 column 16 carries l
    unsigned P[2][8][2];

    for (int c = 0; c < NCH; c++) {
        const int buf = c & 1;
        if (c + 1 < NCH) {
            nk = *(const float4*)(Kbh + (size_t)((c + 1) * BK + kr) * HEADD + ko);
            nv = *(const float4*)(Vbh + (size_t)vd * SS + (c + 1) * BK + vo);
        }

        // ---- S = Q @ K^T, then P = exp2(S) packed fp16 ----
#pragma unroll
        for (int nt = 0; nt < 8; nt++) {
            unsigned b0 = *(const unsigned*)&Ksh[buf][nt * 8 + gr][2 * gc];
            unsigned b1 = *(const unsigned*)&Ksh[buf][nt * 8 + gr][2 * gc + 8];
            float s[4] = {0.f, 0.f, 0.f, 0.f};
            float t[4] = {0.f, 0.f, 0.f, 0.f};
            mma_16816(s, qa[0], b0, b1);
            mma_16816(t, qa[1], b0, b1);
            __half2 p0 = h2exp2(__floats2half2_rn(s[0], s[1]));
            __half2 p1 = h2exp2(__floats2half2_rn(s[2], s[3]));
            __half2 p2 = h2exp2(__floats2half2_rn(t[0], t[1]));
            __half2 p3 = h2exp2(__floats2half2_rn(t[2], t[3]));
            P[0][nt][0] = *(unsigned*)&p0; P[0][nt][1] = *(unsigned*)&p1;
            P[1][nt][0] = *(unsigned*)&p2; P[1][nt][1] = *(unsigned*)&p3;
        }

        // ---- O += P @ Vt (nv=2 tile accumulates l via ones column) ----
#pragma unroll
        for (int kt = 0; kt < 4; kt++) {
            unsigned a0[4] = { P[0][2*kt][0], P[0][2*kt][1],
                               P[0][2*kt+1][0], P[0][2*kt+1][1] };
            unsigned a1[4] = { P[1][2*kt][0], P[1][2*kt][1],
                               P[1][2*kt+1][0], P[1][2*kt+1][1] };
#pragma unroll
            for (int nvt = 0; nvt < 3; nvt++) {
                unsigned b0 = *(const unsigned*)&Vts[buf][nvt * 8 + gr][kt * 16 + 2 * gc];
                unsigned b1 = *(const unsigned*)&Vts[buf][nvt * 8 + gr][kt * 16 + 2 * gc + 8];
                mma_16816(O[0][nvt], a0, b0, b1);
                mma_16816(O[1][nvt], a1, b0, b1);
            }
        }

        __syncthreads();
        if (c + 1 < NCH) {
            *(float4*)&Ksh[buf ^ 1][kr][ko] = nk;
            *(float4*)&Vts[buf ^ 1][vd][vo] = nv;
        }
        __syncthreads();
    }

    // ---- epilogue: normalize by l (column 16) and store ----
    const int b = bh >> 2, h = bh & 3;
#pragma unroll
    for (int mt = 0; mt < 2; mt++) {
        const int srclane = lane & ~3;   // gc==0 lane of this quad holds col 16
        float l_lo = __shfl_sync(0xffffffffu, O[mt][2][0], srclane);
        float l_hi = __shfl_sync(0xffffffffu, O[mt][2][2], srclane);
        const float inv_lo = 1.f / l_lo;
        const float inv_hi = 1.f / l_hi;
        const int r_lo = qrow0 + mt * 16 + gr;
        const int r_hi = r_lo + 8;
#pragma unroll
        for (int nvt = 0; nvt < 2; nvt++) {
            float2 vlo = make_float2(O[mt][nvt][0] * inv_lo, O[mt][nvt][1] * inv_lo);
            float2 vhi = make_float2(O[mt][nvt][2] * inv_hi, O[mt][nvt][3] * inv_hi);
            *(float2*)&g_heads[((size_t)(b * SS) + r_lo) * EMB + h * HEADD + nvt * 8 + 2 * gc] = vlo;
            *(float2*)&g_heads[((size_t)(b * SS) + r_hi) * EMB + h * HEADD + nvt * 8 + 2 * gc] = vhi;
        }
    }
}

// =====================================================================
// Kernel 3: Wo proj + residual + LN1 + FFN(relu) + residual + LN2.
// =====================================================================
__global__ void __launch_bounds__(256) post_kernel(
    const float* __restrict__ data,
    const float* __restrict__ Wo,  const float* __restrict__ bo,
    const float* __restrict__ g1,  const float* __restrict__ bl1,
    const float* __restrict__ W1,  const float* __restrict__ b1,
    const float* __restrict__ W2,  const float* __restrict__ b2,
    const float* __restrict__ g2,  const float* __restrict__ bl2,
    float* __restrict__ out)
{
    __shared__ float Wos[4096];
    __shared__ float W1s[4096];
    __shared__ float W2s[4096];

    const int tid = threadIdx.x;
    for (int i = tid; i < 4096; i += 256) {
        Wos[i] = Wo[i]; W1s[i] = W1[i]; W2s[i] = W2[i];
    }
    __syncthreads();

    const int w    = tid >> 5;
    const int lane = tid & 31;

    const float bo0 = bo[lane],  bo1 = bo[lane + 32];
    const float b10 = b1[lane],  b11 = b1[lane + 32];
    const float b20 = b2[lane],  b21 = b2[lane + 32];
    const float g10 = g1[lane],  g11 = g1[lane + 32];
    const float e10 = bl1[lane], e11 = bl1[lane + 32];
    const float g20 = g2[lane],  g21 = g2[lane + 32];
    const float e20 = bl2[lane], e21 = bl2[lane + 32];

    const int tpw  = NTOK / (gridDim.x * 8);
    const int tok0 = (blockIdx.x * 8 + w) * tpw;

    for (int t = 0; t < tpw; t++) {
        const int tok = tok0 + t;
        const float a0 = g_heads[tok * 64 + lane];
        const float a1 = g_heads[tok * 64 + lane + 32];

        float acc0 = bo0, acc1 = bo1;
#pragma unroll
        for (int d = 0; d < 32; d++) {
            const float xv = __shfl_sync(0xffffffffu, a0, d);
            acc0 = fmaf(xv, Wos[d * 64 + lane],      acc0);
            acc1 = fmaf(xv, Wos[d * 64 + lane + 32], acc1);
        }
#pragma unroll
        for (int d = 32; d < 64; d++) {
            const float xv = __shfl_sync(0xffffffffu, a1, d - 32);
            acc0 = fmaf(xv, Wos[d * 64 + lane],      acc0);
            acc1 = fmaf(xv, Wos[d * 64 + lane + 32], acc1);
        }

        float r0 = data[tok * 64 + lane]      + acc0;
        float r1 = data[tok * 64 + lane + 32] + acc1;

        float mean = warp_sum(r0 + r1) * (1.f / 64.f);
        float d0 = r0 - mean, d1 = r1 - mean;
        float var = warp_sum(d0 * d0 + d1 * d1) * (1.f / 64.f);
        float inv = rsqrtf(var + EPS);
        const float x10 = d0 * inv * g10 + e10;
        const float x11 = d1 * inv * g11 + e11;

        acc0 = b10; acc1 = b11;
#pragma unroll
        for (int d = 0; d < 32; d++) {
            const float xv = __shfl_sync(0xffffffffu, x10, d);
            acc0 = fmaf(xv, W1s[d * 64 + lane],      acc0);
            acc1 = fmaf(xv, W1s[d * 64 + lane + 32], acc1);
        }
#pragma unroll
        for (int d = 32; d < 64; d++) {
            const float xv = __shfl_sync(0xffffffffu, x11, d - 32);
            acc0 = fmaf(xv, W1s[d * 64 + lane],      acc0);
            acc1 = fmaf(xv, W1s[d * 64 + lane + 32], acc1);
        }
        const float h0 = fmaxf(acc0, 0.f);
        const float h1 = fmaxf(acc1, 0.f);

        acc0 = b20; acc1 = b21;
#pragma unroll
        for (int d = 0; d < 32; d++) {
            const float xv = __shfl_sync(0xffffffffu, h0, d);
            acc0 = fmaf(xv, W2s[d * 64 + lane],      acc0);
            acc1 = fmaf(xv, W2s[d * 64 + lane + 32], acc1);
        }
#pragma unroll
        for (int d = 32; d < 64; d++) {
            const float xv = __shfl_sync(0xffffffffu, h1, d - 32);
            acc0 = fmaf(xv, W2s[d * 64 + lane],      acc0);
            acc1 = fmaf(xv, W2s[d * 64 + lane + 32], acc1);
        }

        r0 = acc0 + x10;
        r1 = acc1 + x11;

        mean = warp_sum(r0 + r1) * (1.f / 64.f);
        d0 = r0 - mean; d1 = r1 - mean;
        var = warp_sum(d0 * d0 + d1 * d1) * (1.f / 64.f);
        inv = rsqrtf(var + EPS);

        out[tok * 64 + lane]      = d0 * inv * g20 + e20;
        out[tok * 64 + lane + 32] = d1 * inv * g21 + e21;
    }
}

// =====================================================================
extern "C" void kernel_launch(void* const* d_in, const int* in_sizes, int n_in,
                              void* d_out, int out_size)
{
    const float* data  = (const float*)d_in[0];
    const float* Wq    = (const float*)d_in[1];
    const float* Wk    = (const float*)d_in[2];
    const float* Wv    = (const float*)d_in[3];
    const float* Wo    = (const float*)d_in[4];
    const float* bo    = (const float*)d_in[5];
    const float* ln1_g = (const float*)d_in[6];
    const float* ln1_b = (const float*)d_in[7];
    const float* W1    = (const float*)d_in[8];
    const float* b1    = (const float*)d_in[9];
    const float* W2    = (const float*)d_in[10];
    const float* b2    = (const float*)d_in[11];
    const float* ln2_g = (const float*)d_in[12];
    const float* ln2_b = (const float*)d_in[13];
    float* out = (float*)d_out;

    qkv_kernel<<<512, 256>>>(data, Wq, Wk, Wv);
    attn_kernel<<<dim3(NHEAD * BB, SS / 128), 128>>>();
    post_kernel<<<512, 256>>>(data, Wo, bo, ln1_g, ln1_b, W1, b1,
                              W2, b2, ln2_g, ln2_b, out);
}

// round 6
// speedup vs baseline: 3.4243x; 1.2571x over previous
#include <cuda_runtime.h>
#include <cuda_fp16.h>
#include <math.h>

#define EMB    64
#define NHEAD  4
#define HEADD  16
#define BB     8
#define SS     2048
#define NTOK   (BB*SS)            // 16384
#define EPS    1e-5f
// exp2-domain scale: 1/sqrt(16) * log2(e)
#define QSCALE (0.25f * 1.44269504088896f)

#define BK     64                 // keys per chunk
#define NCH    (SS/BK)            // 32

// ---------------- device scratch (no allocations allowed) ----------------
// per-head layouts: [bh][s][16] with bh in [0, BB*NHEAD) -> NTOK*EMB halves total
__device__ __align__(16) __half g_Qh[NTOK*EMB];   // [bh][s][16], QSCALE folded in
__device__ __align__(16) __half g_Kh[NTOK*EMB];   // [bh][s][16]
__device__ __align__(16) __half g_Vt[NTOK*EMB];   // [bh][16][s]  (transposed!)
__device__ __align__(16) float  g_heads[NTOK*EMB];  // concat layout [b][s][h*16+k]

__device__ __forceinline__ float warp_sum(float v) {
#pragma unroll
    for (int o = 16; o > 0; o >>= 1) v += __shfl_xor_sync(0xffffffffu, v, o);
    return v;
}

__device__ __forceinline__ void mma_16816(float* d, const unsigned* a,
                                          unsigned b0, unsigned b1) {
    asm volatile(
        "mma.sync.aligned.m16n8k16.row.col.f32.f16.f16.f32 "
        "{%0,%1,%2,%3}, {%4,%5,%6,%7}, {%8,%9}, {%0,%1,%2,%3};\n"
        : "+f"(d[0]), "+f"(d[1]), "+f"(d[2]), "+f"(d[3])
        : "r"(a[0]), "r"(a[1]), "r"(a[2]), "r"(a[3]), "r"(b0), "r"(b1));
}

// =====================================================================
// Kernel 1: QKV projection on tensor cores.
// GEMM [NTOK x 64] @ [64 x 192] (cols = Q|K|V, QSCALE folded into Q).
// Block = 128 threads (4 warps); each warp does one 16-token M-tile.
// =====================================================================
__global__ void __launch_bounds__(128) qkv_kernel(
    const float* __restrict__ data,
    const float* __restrict__ Wq,
    const float* __restrict__ Wk,
    const float* __restrict__ Wv)
{
    // Wt[n][k], n = output col (0..191), k contiguous, stride 72 halves
    __shared__ __align__(16) __half Wt[192 * 72];

    const int tid  = threadIdx.x;
    const int warp = tid >> 5;
    const int lane = tid & 31;
    const int gr   = lane >> 2;   // 0..7
    const int gc   = lane & 3;    // 0..3

    for (int i = tid; i < 192 * 64; i += 128) {
        const int k = i / 192, n = i % 192;
        float w;
        if (n < 64)        w = Wq[(n >> 4) * 1024 + k * 16 + (n & 15)] * QSCALE;
        else if (n < 128)  w = Wk[((n - 64) >> 4) * 1024 + k * 16 + ((n - 64) & 15)];
        else               w = Wv[((n - 128) >> 4) * 1024 + k * 16 + ((n - 128) & 15)];
        Wt[n * 72 + k] = __float2half_rn(w);
    }
    __syncthreads();

    const int tile = blockIdx.x * 4 + warp;   // 0..1023
    const int tok0 = tile * 16;

    // A fragments: 16 tokens x 64 dims, fp32 -> fp16
    unsigned a[4][4];
#pragma unroll
    for (int kt = 0; kt < 4; kt++) {
        const float* r0 = data + (size_t)(tok0 + gr) * 64 + kt * 16 + 2 * gc;
        const float* r8 = r0 + 8 * 64;
        float2 x0 = *(const float2*)r0;
        float2 x8 = *(const float2*)r8;
        float2 y0 = *(const float2*)(r0 + 8);
        float2 y8 = *(const float2*)(r8 + 8);
        __half2 h0 = __floats2half2_rn(x0.x, x0.y);
        __half2 h1 = __floats2half2_rn(x8.x, x8.y);
        __half2 h2 = __floats2half2_rn(y0.x, y0.y);
        __half2 h3 = __floats2half2_rn(y8.x, y8.y);
        a[kt][0] = *(unsigned*)&h0; a[kt][1] = *(unsigned*)&h1;
        a[kt][2] = *(unsigned*)&h2; a[kt][3] = *(unsigned*)&h3;
    }

    float acc[24][4] = {};
#pragma unroll
    for (int nt = 0; nt < 24; nt++) {
#pragma unroll
        for (int kt = 0; kt < 4; kt++) {
            const __half* base = &Wt[(nt * 8 + gr) * 72 + kt * 16 + 2 * gc];
            unsigned b0 = *(const unsigned*)base;
            unsigned b1 = *(const unsigned*)(base + 8);
            mma_16816(acc[nt], a[kt], b0, b1);
        }
    }

    // ---- epilogue ----
    const int b  = tok0 >> 11;
    const int sb = tok0 & 2047;

#pragma unroll
    for (int nt = 0; nt < 8; nt++) {           // Q
        const int head = nt >> 1;
        const int kk0  = (nt & 1) * 8 + 2 * gc;
        const size_t base = (size_t)(b * 4 + head) * 2048;
        __half2 lo = __floats2half2_rn(acc[nt][0], acc[nt][1]);
        __half2 hi = __floats2half2_rn(acc[nt][2], acc[nt][3]);
        *(__half2*)&g_Qh[(base + sb + gr)     * 16 + kk0] = lo;
        *(__half2*)&g_Qh[(base + sb + gr + 8) * 16 + kk0] = hi;
    }
#pragma unroll
    for (int nt = 0; nt < 8; nt++) {           // K
        const int head = nt >> 1;
        const int kk0  = (nt & 1) * 8 + 2 * gc;
        const size_t base = (size_t)(b * 4 + head) * 2048;
        __half2 lo = __floats2half2_rn(acc[8 + nt][0], acc[8 + nt][1]);
        __half2 hi = __floats2half2_rn(acc[8 + nt][2], acc[8 + nt][3]);
        *(__half2*)&g_Kh[(base + sb + gr)     * 16 + kk0] = lo;
        *(__half2*)&g_Kh[(base + sb + gr + 8) * 16 + kk0] = hi;
    }
#pragma unroll
    for (int nt = 0; nt < 8; nt++) {           // V (transposed store)
        const int vcol = nt * 8 + 2 * gc;
        const int head = vcol >> 4;
        const int kk   = vcol & 15;
        const size_t base = (size_t)(b * 4 + head) * 16;
        g_Vt[(base + kk)     * 2048 + sb + gr]     = __float2half_rn(acc[16 + nt][0]);
        g_Vt[(base + kk + 1) * 2048 + sb + gr]     = __float2half_rn(acc[16 + nt][1]);
        g_Vt[(base + kk)     * 2048 + sb + gr + 8] = __float2half_rn(acc[16 + nt][2]);
        g_Vt[(base + kk + 1) * 2048 + sb + gr + 8] = __float2half_rn(acc[16 + nt][3]);
    }
}

// =====================================================================
// Kernel 2: fp16 tensor-core flash attention (no-max softmax).
// Block: 128 threads (4 warps), 128 query rows; warp = 32 rows.
// Per chunk: S = Q@K^T (mma), P = exp2(S) in fp16, O += P@[V | 1 0..]
// =====================================================================
__global__ void __launch_bounds__(128) attn_kernel()
{
    __shared__ __align__(16) __half Ksh[2][BK][24];   // stride 24 halves (48B)
    __shared__ __align__(16) __half Vts[2][24][72];   // [dim(+l cols)][key]

    const int bh   = blockIdx.x;
    const int tid  = threadIdx.x;
    const int warp = tid >> 5;
    const int lane = tid & 31;
    const int gr   = lane >> 2;   // 0..7
    const int gc   = lane & 3;    // 0..3
    const int qrow0 = blockIdx.y * 128 + warp * 32;

    // constant rows 16..23 of Vt tiles: dim16 = ones (row-sum column), rest 0
    for (int i = tid; i < 2 * 8 * 72; i += 128) {
        int bufi = i / (8 * 72);
        int rem  = i % (8 * 72);
        int r = rem / 72, cc = rem % 72;
        Vts[bufi][16 + r][cc] = __float2half(r == 0 ? 1.0f : 0.0f);
    }

    // Q fragments (held for whole kernel)
    const __half* Qbh = g_Qh + (size_t)bh * SS * HEADD;
    unsigned qa[2][4];
#pragma unroll
    for (int mt = 0; mt < 2; mt++) {
        const __half* r0 = Qbh + (size_t)(qrow0 + mt * 16 + gr) * HEADD;
        qa[mt][0] = *(const unsigned*)(r0 + 2 * gc);
        qa[mt][1] = *(const unsigned*)(r0 + 8 * HEADD + 2 * gc);
        qa[mt][2] = *(const unsigned*)(r0 + 2 * gc + 8);
        qa[mt][3] = *(const unsigned*)(r0 + 8 * HEADD + 2 * gc + 8);
    }

    const __half* Kbh = g_Kh + (size_t)bh * SS * HEADD;
    const __half* Vbh = g_Vt + (size_t)bh * HEADD * SS;

    const int kr = tid >> 1, ko = (tid & 1) * 8;   // K: row, half-offset
    const int vd = tid >> 3, vo = (tid & 7) * 8;   // V: dim, key-offset

    float4 nk = *(const float4*)(Kbh + (size_t)kr * HEADD + ko);
    float4 nv = *(const float4*)(Vbh + (size_t)vd * SS + vo);
    *(float4*)&Ksh[0][kr][ko] = nk;
    *(float4*)&Vts[0][vd][vo] = nv;
    __syncthreads();

    float O[2][3][4] = {};    // [mt][nv-tile][frag]; nv=2 column 16 carries l
    unsigned P[2][8][2];

    for (int c = 0; c < NCH; c++) {
        const int buf = c & 1;
        if (c + 1 < NCH) {
            nk = *(const float4*)(Kbh + (size_t)((c + 1) * BK + kr) * HEADD + ko);
            nv = *(const float4*)(Vbh + (size_t)vd * SS + (c + 1) * BK + vo);
        }

        // ---- S = Q @ K^T, then P = exp2(S) packed fp16 ----
#pragma unroll
        for (int nt = 0; nt < 8; nt++) {
            unsigned b0 = *(const unsigned*)&Ksh[buf][nt * 8 + gr][2 * gc];
            unsigned b1 = *(const unsigned*)&Ksh[buf][nt * 8 + gr][2 * gc + 8];
            float s[4] = {0.f, 0.f, 0.f, 0.f};
            float t[4] = {0.f, 0.f, 0.f, 0.f};
            mma_16816(s, qa[0], b0, b1);
            mma_16816(t, qa[1], b0, b1);
            __half2 p0 = h2exp2(__floats2half2_rn(s[0], s[1]));
            __half2 p1 = h2exp2(__floats2half2_rn(s[2], s[3]));
            __half2 p2 = h2exp2(__floats2half2_rn(t[0], t[1]));
            __half2 p3 = h2exp2(__floats2half2_rn(t[2], t[3]));
            P[0][nt][0] = *(unsigned*)&p0; P[0][nt][1] = *(unsigned*)&p1;
            P[1][nt][0] = *(unsigned*)&p2; P[1][nt][1] = *(unsigned*)&p3;
        }

        // ---- O += P @ Vt (nv=2 tile accumulates l via ones column) ----
#pragma unroll
        for (int kt = 0; kt < 4; kt++) {
            unsigned a0[4] = { P[0][2*kt][0], P[0][2*kt][1],
                               P[0][2*kt+1][0], P[0][2*kt+1][1] };
            unsigned a1[4] = { P[1][2*kt][0], P[1][2*kt][1],
                               P[1][2*kt+1][0], P[1][2*kt+1][1] };
#pragma unroll
            for (int nvt = 0; nvt < 3; nvt++) {
                unsigned b0 = *(const unsigned*)&Vts[buf][nvt * 8 + gr][kt * 16 + 2 * gc];
                unsigned b1 = *(const unsigned*)&Vts[buf][nvt * 8 + gr][kt * 16 + 2 * gc + 8];
                mma_16816(O[0][nvt], a0, b0, b1);
                mma_16816(O[1][nvt], a1, b0, b1);
            }
        }

        __syncthreads();
        if (c + 1 < NCH) {
            *(float4*)&Ksh[buf ^ 1][kr][ko] = nk;
            *(float4*)&Vts[buf ^ 1][vd][vo] = nv;
        }
        __syncthreads();
    }

    // ---- epilogue: normalize by l (column 16) and store ----
    const int b = bh >> 2, h = bh & 3;
#pragma unroll
    for (int mt = 0; mt < 2; mt++) {
        const int srclane = lane & ~3;   // gc==0 lane of this quad holds col 16
        float l_lo = __shfl_sync(0xffffffffu, O[mt][2][0], srclane);
        float l_hi = __shfl_sync(0xffffffffu, O[mt][2][2], srclane);
        const float inv_lo = 1.f / l_lo;
        const float inv_hi = 1.f / l_hi;
        const int r_lo = qrow0 + mt * 16 + gr;
        const int r_hi = r_lo + 8;
#pragma unroll
        for (int nvt = 0; nvt < 2; nvt++) {
            float2 vlo = make_float2(O[mt][nvt][0] * inv_lo, O[mt][nvt][1] * inv_lo);
            float2 vhi = make_float2(O[mt][nvt][2] * inv_hi, O[mt][nvt][3] * inv_hi);
            *(float2*)&g_heads[((size_t)(b * SS) + r_lo) * EMB + h * HEADD + nvt * 8 + 2 * gc] = vlo;
            *(float2*)&g_heads[((size_t)(b * SS) + r_hi) * EMB + h * HEADD + nvt * 8 + 2 * gc] = vhi;
        }
    }
}

// =====================================================================
// Kernel 3: Wo proj + residual + LN1 + FFN(relu) + residual + LN2.
// 2 tokens per loop iteration: weight LDS amortized across both tokens.
// =====================================================================
__global__ void __launch_bounds__(256) post_kernel(
    const float* __restrict__ data,
    const float* __restrict__ Wo,  const float* __restrict__ bo,
    const float* __restrict__ g1,  const float* __restrict__ bl1,
    const float* __restrict__ W1,  const float* __restrict__ b1,
    const float* __restrict__ W2,  const float* __restrict__ b2,
    const float* __restrict__ g2,  const float* __restrict__ bl2,
    float* __restrict__ out)
{
    __shared__ float Wos[4096];
    __shared__ float W1s[4096];
    __shared__ float W2s[4096];

    const int tid = threadIdx.x;
    for (int i = tid; i < 4096; i += 256) {
        Wos[i] = Wo[i]; W1s[i] = W1[i]; W2s[i] = W2[i];
    }
    __syncthreads();

    const int w    = tid >> 5;
    const int lane = tid & 31;

    const float bo0 = bo[lane],  bo1 = bo[lane + 32];
    const float b10 = b1[lane],  b11 = b1[lane + 32];
    const float b20 = b2[lane],  b21 = b2[lane + 32];
    const float g10 = g1[lane],  g11 = g1[lane + 32];
    const float e10 = bl1[lane], e11 = bl1[lane + 32];
    const float g20 = g2[lane],  g21 = g2[lane + 32];
    const float e20 = bl2[lane], e21 = bl2[lane + 32];

    const int tpw  = NTOK / (gridDim.x * 8);
    const int tok0 = (blockIdx.x * 8 + w) * tpw;

    for (int t = 0; t < tpw; t += 2) {
        const int tokA = tok0 + t;
        const int tokB = tokA + 1;
        float aA0 = g_heads[tokA * 64 + lane];
        float aA1 = g_heads[tokA * 64 + lane + 32];
        float aB0 = g_heads[tokB * 64 + lane];
        float aB1 = g_heads[tokB * 64 + lane + 32];

        // attn_out = a @ Wo + bo   (both tokens share weight loads)
        float A0 = bo0, A1 = bo1, B0 = bo0, B1 = bo1;
#pragma unroll
        for (int d = 0; d < 32; d++) {
            const float w0 = Wos[d * 64 + lane];
            const float w1 = Wos[d * 64 + lane + 32];
            const float xA = __shfl_sync(0xffffffffu, aA0, d);
            const float xB = __shfl_sync(0xffffffffu, aB0, d);
            A0 = fmaf(xA, w0, A0); A1 = fmaf(xA, w1, A1);
            B0 = fmaf(xB, w0, B0); B1 = fmaf(xB, w1, B1);
        }
#pragma unroll
        for (int d = 32; d < 64; d++) {
            const float w0 = Wos[d * 64 + lane];
            const float w1 = Wos[d * 64 + lane + 32];
            const float xA = __shfl_sync(0xffffffffu, aA1, d - 32);
            const float xB = __shfl_sync(0xffffffffu, aB1, d - 32);
            A0 = fmaf(xA, w0, A0); A1 = fmaf(xA, w1, A1);
            B0 = fmaf(xB, w0, B0); B1 = fmaf(xB, w1, B1);
        }

        float rA0 = data[tokA * 64 + lane]      + A0;
        float rA1 = data[tokA * 64 + lane + 32] + A1;
        float rB0 = data[tokB * 64 + lane]      + B0;
        float rB1 = data[tokB * 64 + lane + 32] + B1;

        // LN1 (per token)
        float meanA = warp_sum(rA0 + rA1) * (1.f / 64.f);
        float meanB = warp_sum(rB0 + rB1) * (1.f / 64.f);
        float dA0 = rA0 - meanA, dA1 = rA1 - meanA;
        float dB0 = rB0 - meanB, dB1 = rB1 - meanB;
        float varA = warp_sum(dA0 * dA0 + dA1 * dA1) * (1.f / 64.f);
        float varB = warp_sum(dB0 * dB0 + dB1 * dB1) * (1.f / 64.f);
        float ivA = rsqrtf(varA + EPS);
        float ivB = rsqrtf(varB + EPS);
        const float xA10 = dA0 * ivA * g10 + e10;
        const float xA11 = dA1 * ivA * g11 + e11;
        const float xB10 = dB0 * ivB * g10 + e10;
        const float xB11 = dB1 * ivB * g11 + e11;

        // h = relu(x1 @ W1 + b1)
        A0 = b10; A1 = b11; B0 = b10; B1 = b11;
#pragma unroll
        for (int d = 0; d < 32; d++) {
            const float w0 = W1s[d * 64 + lane];
            const float w1 = W1s[d * 64 + lane + 32];
            const float xA = __shfl_sync(0xffffffffu, xA10, d);
            const float xB = __shfl_sync(0xffffffffu, xB10, d);
            A0 = fmaf(xA, w0, A0); A1 = fmaf(xA, w1, A1);
            B0 = fmaf(xB, w0, B0); B1 = fmaf(xB, w1, B1);
        }
#pragma unroll
        for (int d = 32; d < 64; d++) {
            const float w0 = W1s[d * 64 + lane];
            const float w1 = W1s[d * 64 + lane + 32];
            const float xA = __shfl_sync(0xffffffffu, xA11, d - 32);
            const float xB = __shfl_sync(0xffffffffu, xB11, d - 32);
            A0 = fmaf(xA, w0, A0); A1 = fmaf(xA, w1, A1);
            B0 = fmaf(xB, w0, B0); B1 = fmaf(xB, w1, B1);
        }
        const float hA0 = fmaxf(A0, 0.f), hA1 = fmaxf(A1, 0.f);
        const float hB0 = fmaxf(B0, 0.f), hB1 = fmaxf(B1, 0.f);

        // ff = h @ W2 + b2
        A0 = b20; A1 = b21; B0 = b20; B1 = b21;
#pragma unroll
        for (int d = 0; d < 32; d++) {
            const float w0 = W2s[d * 64 + lane];
            const float w1 = W2s[d * 64 + lane + 32];
            const float xA = __shfl_sync(0xffffffffu, hA0, d);
            const float xB = __shfl_sync(0xffffffffu, hB0, d);
            A0 = fmaf(xA, w0, A0); A1 = fmaf(xA, w1, A1);
            B0 = fmaf(xB, w0, B0); B1 = fmaf(xB, w1, B1);
        }
#pragma unroll
        for (int d = 32; d < 64; d++) {
            const float w0 = W2s[d * 64 + lane];
            const float w1 = W2s[d * 64 + lane + 32];
            const float xA = __shfl_sync(0xffffffffu, hA1, d - 32);
            const float xB = __shfl_sync(0xffffffffu, hB1, d - 32);
            A0 = fmaf(xA, w0, A0); A1 = fmaf(xA, w1, A1);
            B0 = fmaf(xB, w0, B0); B1 = fmaf(xB, w1, B1);
        }

        rA0 = A0 + xA10; rA1 = A1 + xA11;
        rB0 = B0 + xB10; rB1 = B1 + xB11;

        // LN2 (per token)
        meanA = warp_sum(rA0 + rA1) * (1.f / 64.f);
        meanB = warp_sum(rB0 + rB1) * (1.f / 64.f);
        dA0 = rA0 - meanA; dA1 = rA1 - meanA;
        dB0 = rB0 - meanB; dB1 = rB1 - meanB;
        varA = warp_sum(dA0 * dA0 + dA1 * dA1) * (1.f / 64.f);
        varB = warp_sum(dB0 * dB0 + dB1 * dB1) * (1.f / 64.f);
        ivA = rsqrtf(varA + EPS);
        ivB = rsqrtf(varB + EPS);

        out[tokA * 64 + lane]      = dA0 * ivA * g20 + e20;
        out[tokA * 64 + lane + 32] = dA1 * ivA * g21 + e21;
        out[tokB * 64 + lane]      = dB0 * ivB * g20 + e20;
        out[tokB * 64 + lane + 32] = dB1 * ivB * g21 + e21;
    }
}

// =====================================================================
extern "C" void kernel_launch(void* const* d_in, const int* in_sizes, int n_in,
                              void* d_out, int out_size)
{
    const float* data  = (const float*)d_in[0];
    const float* Wq    = (const float*)d_in[1];
    const float* Wk    = (const float*)d_in[2];
    const float* Wv    = (const float*)d_in[3];
    const float* Wo    = (const float*)d_in[4];
    const float* bo    = (const float*)d_in[5];
    const float* ln1_g = (const float*)d_in[6];
    const float* ln1_b = (const float*)d_in[7];
    const float* W1    = (const float*)d_in[8];
    const float* b1    = (const float*)d_in[9];
    const float* W2    = (const float*)d_in[10];
    const float* b2    = (const float*)d_in[11];
    const float* ln2_g = (const float*)d_in[12];
    const float* ln2_b = (const float*)d_in[13];
    float* out = (float*)d_out;

    qkv_kernel<<<256, 128>>>(data, Wq, Wk, Wv);
    attn_kernel<<<dim3(NHEAD * BB, SS / 128), 128>>>();
    post_kernel<<<512, 256>>>(data, Wo, bo, ln1_g, ln1_b, W1, b1,
                              W2, b2, ln2_g, ln2_b, out);
}

// round 7
// speedup vs baseline: 4.0000x; 1.1681x over previous
#include <cuda_runtime.h>
#include <cuda_fp16.h>
#include <math.h>

#define EMB    64
#define NHEAD  4
#define HEADD  16
#define BB     8
#define SS     2048
#define NTOK   (BB*SS)            // 16384
#define EPS    1e-5f
// exp2-domain scale: 1/sqrt(16) * log2(e)
#define QSCALE (0.25f * 1.44269504088896f)

#define BK     64                 // keys per chunk
#define NCH    (SS/BK)            // 32

// ---------------- device scratch (no allocations allowed) ----------------
__device__ __align__(16) __half g_Qh[NTOK*EMB];   // [bh][s][16], QSCALE folded in
__device__ __align__(16) __half g_Kh[NTOK*EMB];   // [bh][s][16]
__device__ __align__(16) __half g_Vt[NTOK*EMB];   // [bh][16][s]  (transposed!)
__device__ __align__(16) float  g_heads[NTOK*EMB];  // concat layout [b][s][h*16+k]
__device__ __align__(16) __half g_Wth[192*72];    // pre-converted QKV weights [n][k]

__device__ __forceinline__ float warp_sum(float v) {
#pragma unroll
    for (int o = 16; o > 0; o >>= 1) v += __shfl_xor_sync(0xffffffffu, v, o);
    return v;
}

__device__ __forceinline__ void mma_16816(float* d, const unsigned* a,
                                          unsigned b0, unsigned b1) {
    asm volatile(
        "mma.sync.aligned.m16n8k16.row.col.f32.f16.f16.f32 "
        "{%0,%1,%2,%3}, {%4,%5,%6,%7}, {%8,%9}, {%0,%1,%2,%3};\n"
        : "+f"(d[0]), "+f"(d[1]), "+f"(d[2]), "+f"(d[3])
        : "r"(a[0]), "r"(a[1]), "r"(a[2]), "r"(a[3]), "r"(b0), "r"(b1));
}

// =====================================================================
// Kernel 0: one-time weight conversion to fp16 B-fragment layout.
// g_Wth[n*72+k], n = output col (Q|K|V = 0..191), k = input dim.
// =====================================================================
__global__ void prep_kernel(const float* __restrict__ Wq,
                            const float* __restrict__ Wk,
                            const float* __restrict__ Wv)
{
    const int i = blockIdx.x * 256 + threadIdx.x;
    if (i >= 192 * 64) return;
    const int n = i % 192, k = i / 192;
    float w;
    if (n < 64)        w = Wq[(n >> 4) * 1024 + k * 16 + (n & 15)] * QSCALE;
    else if (n < 128)  w = Wk[((n - 64) >> 4) * 1024 + k * 16 + ((n - 64) & 15)];
    else               w = Wv[((n - 128) >> 4) * 1024 + k * 16 + ((n - 128) & 15)];
    g_Wth[n * 72 + k] = __float2half_rn(w);
}

// =====================================================================
// Kernel 1: QKV projection on tensor cores.
// GEMM [NTOK x 64] @ [64 x 192]; warp = 16-token M-tile, block = 64 tokens.
// Weights loaded as uint4 from pre-converted g_Wth; V transposed through
// a smem stage so g_Vt stores are coalesced 16B.
// =====================================================================
__global__ void __launch_bounds__(128) qkv_kernel(const float* __restrict__ data)
{
    __shared__ __align__(16) __half Wt[192 * 72];     // 27648 B
    __shared__ __align__(16) __half stage_v[64 * 66]; // 8448 B, odd-word stride

    const int tid  = threadIdx.x;
    const int warp = tid >> 5;
    const int lane = tid & 31;
    const int gr   = lane >> 2;   // 0..7
    const int gc   = lane & 3;    // 0..3

    {   // vectorized weight load: 27648 B = 1728 uint4
        const uint4* src = (const uint4*)g_Wth;
        uint4* dst = (uint4*)Wt;
        for (int i = tid; i < 1728; i += 128) dst[i] = src[i];
    }
    __syncthreads();

    const int tile = blockIdx.x * 4 + warp;   // 0..1023
    const int tok0 = tile * 16;

    // A fragments: 16 tokens x 64 dims, fp32 -> fp16
    unsigned a[4][4];
#pragma unroll
    for (int kt = 0; kt < 4; kt++) {
        const float* r0 = data + (size_t)(tok0 + gr) * 64 + kt * 16 + 2 * gc;
        const float* r8 = r0 + 8 * 64;
        float2 x0 = *(const float2*)r0;
        float2 x8 = *(const float2*)r8;
        float2 y0 = *(const float2*)(r0 + 8);
        float2 y8 = *(const float2*)(r8 + 8);
        __half2 h0 = __floats2half2_rn(x0.x, x0.y);
        __half2 h1 = __floats2half2_rn(x8.x, x8.y);
        __half2 h2 = __floats2half2_rn(y0.x, y0.y);
        __half2 h3 = __floats2half2_rn(y8.x, y8.y);
        a[kt][0] = *(unsigned*)&h0; a[kt][1] = *(unsigned*)&h1;
        a[kt][2] = *(unsigned*)&h2; a[kt][3] = *(unsigned*)&h3;
    }

    float acc[24][4] = {};
#pragma unroll
    for (int nt = 0; nt < 24; nt++) {
#pragma unroll
        for (int kt = 0; kt < 4; kt++) {
            const __half* base = &Wt[(nt * 8 + gr) * 72 + kt * 16 + 2 * gc];
            unsigned b0 = *(const unsigned*)base;
            unsigned b1 = *(const unsigned*)(base + 8);
            mma_16816(acc[nt], a[kt], b0, b1);
        }
    }

    // ---- stage V fragments to smem (for transposed coalesced store) ----
#pragma unroll
    for (int nt = 0; nt < 8; nt++) {
        const int vcol = nt * 8 + 2 * gc;
        __half2 lo = __floats2half2_rn(acc[16 + nt][0], acc[16 + nt][1]);
        __half2 hi = __floats2half2_rn(acc[16 + nt][2], acc[16 + nt][3]);
        *(__half2*)&stage_v[(warp * 16 + gr)     * 66 + vcol] = lo;
        *(__half2*)&stage_v[(warp * 16 + gr + 8) * 66 + vcol] = hi;
    }
    __syncthreads();

    // ---- direct Q/K stores (half2, quad-contiguous 16B segments) ----
    const int b  = tok0 >> 11;
    const int sb = tok0 & 2047;
#pragma unroll
    for (int nt = 0; nt < 8; nt++) {           // Q
        const int head = nt >> 1;
        const int kk0  = (nt & 1) * 8 + 2 * gc;
        const size_t base = (size_t)(b * 4 + head) * 2048;
        __half2 lo = __floats2half2_rn(acc[nt][0], acc[nt][1]);
        __half2 hi = __floats2half2_rn(acc[nt][2], acc[nt][3]);
        *(__half2*)&g_Qh[(base + sb + gr)     * 16 + kk0] = lo;
        *(__half2*)&g_Qh[(base + sb + gr + 8) * 16 + kk0] = hi;
    }
#pragma unroll
    for (int nt = 0; nt < 8; nt++) {           // K
        const int head = nt >> 1;
        const int kk0  = (nt & 1) * 8 + 2 * gc;
        const size_t base = (size_t)(b * 4 + head) * 2048;
        __half2 lo = __floats2half2_rn(acc[8 + nt][0], acc[8 + nt][1]);
        __half2 hi = __floats2half2_rn(acc[8 + nt][2], acc[8 + nt][3]);
        *(__half2*)&g_Kh[(base + sb + gr)     * 16 + kk0] = lo;
        *(__half2*)&g_Kh[(base + sb + gr + 8) * 16 + kk0] = hi;
    }

    // ---- cooperative coalesced V store: 512 uint4, 8 threads per row ----
    const int s0 = (blockIdx.x * 64) & 2047;
    const int bb = (blockIdx.x * 64) >> 11;
#pragma unroll
    for (int q = 0; q < 4; q++) {
        const int idx = q * 128 + tid;      // 0..511
        const int c   = idx >> 3;           // vcol 0..63
        const int j   = idx & 7;            // 8-half group within row
        const int h   = c >> 4;
        const int kk  = c & 15;
        __half t0 = stage_v[(8 * j + 0) * 66 + c];
        __half t1 = stage_v[(8 * j + 1) * 66 + c];
        __half t2 = stage_v[(8 * j + 2) * 66 + c];
        __half t3 = stage_v[(8 * j + 3) * 66 + c];
        __half t4 = stage_v[(8 * j + 4) * 66 + c];
        __half t5 = stage_v[(8 * j + 5) * 66 + c];
        __half t6 = stage_v[(8 * j + 6) * 66 + c];
        __half t7 = stage_v[(8 * j + 7) * 66 + c];
        __half2 p0 = __halves2half2(t0, t1);
        __half2 p1 = __halves2half2(t2, t3);
        __half2 p2 = __halves2half2(t4, t5);
        __half2 p3 = __halves2half2(t6, t7);
        uint4 u;
        u.x = *(unsigned*)&p0; u.y = *(unsigned*)&p1;
        u.z = *(unsigned*)&p2; u.w = *(unsigned*)&p3;
        *(uint4*)&g_Vt[((size_t)(bb * 4 + h) * 16 + kk) * 2048 + s0 + 8 * j] = u;
    }
}

// =====================================================================
// Kernel 2: fp16 tensor-core flash attention (no-max softmax).
// =====================================================================
__global__ void __launch_bounds__(128) attn_kernel()
{
    __shared__ __align__(16) __half Ksh[2][BK][24];   // stride 24 halves (48B)
    __shared__ __align__(16) __half Vts[2][24][72];   // [dim(+l cols)][key]

    const int bh   = blockIdx.x;
    const int tid  = threadIdx.x;
    const int warp = tid >> 5;
    const int lane = tid & 31;
    const int gr   = lane >> 2;   // 0..7
    const int gc   = lane & 3;    // 0..3
    const int qrow0 = blockIdx.y * 128 + warp * 32;

    // constant rows 16..23 of Vt tiles: dim16 = ones (row-sum column), rest 0
    for (int i = tid; i < 2 * 8 * 72; i += 128) {
        int bufi = i / (8 * 72);
        int rem  = i % (8 * 72);
        int r = rem / 72, cc = rem % 72;
        Vts[bufi][16 + r][cc] = __float2half(r == 0 ? 1.0f : 0.0f);
    }

    // Q fragments (held for whole kernel)
    const __half* Qbh = g_Qh + (size_t)bh * SS * HEADD;
    unsigned qa[2][4];
#pragma unroll
    for (int mt = 0; mt < 2; mt++) {
        const __half* r0 = Qbh + (size_t)(qrow0 + mt * 16 + gr) * HEADD;
        qa[mt][0] = *(const unsigned*)(r0 + 2 * gc);
        qa[mt][1] = *(const unsigned*)(r0 + 8 * HEADD + 2 * gc);
        qa[mt][2] = *(const unsigned*)(r0 + 2 * gc + 8);
        qa[mt][3] = *(const unsigned*)(r0 + 8 * HEADD + 2 * gc + 8);
    }

    const __half* Kbh = g_Kh + (size_t)bh * SS * HEADD;
    const __half* Vbh = g_Vt + (size_t)bh * HEADD * SS;

    const int kr = tid >> 1, ko = (tid & 1) * 8;   // K: row, half-offset
    const int vd = tid >> 3, vo = (tid & 7) * 8;   // V: dim, key-offset

    float4 nk = *(const float4*)(Kbh + (size_t)kr * HEADD + ko);
    float4 nv = *(const float4*)(Vbh + (size_t)vd * SS + vo);
    *(float4*)&Ksh[0][kr][ko] = nk;
    *(float4*)&Vts[0][vd][vo] = nv;
    __syncthreads();

    float O[2][3][4] = {};    // [mt][nv-tile][frag]; nv=2 column 16 carries l
    unsigned P[2][8][2];

    for (int c = 0; c < NCH; c++) {
        const int buf = c & 1;
        if (c + 1 < NCH) {
            nk = *(const float4*)(Kbh + (size_t)((c + 1) * BK + kr) * HEADD + ko);
            nv = *(const float4*)(Vbh + (size_t)vd * SS + (c + 1) * BK + vo);
        }

        // ---- S = Q @ K^T, then P = exp2(S) packed fp16 ----
#pragma unroll
        for (int nt = 0; nt < 8; nt++) {
            unsigned b0 = *(const unsigned*)&Ksh[buf][nt * 8 + gr][2 * gc];
            unsigned b1 = *(const unsigned*)&Ksh[buf][nt * 8 + gr][2 * gc + 8];
            float s[4] = {0.f, 0.f, 0.f, 0.f};
            float t[4] = {0.f, 0.f, 0.f, 0.f};
            mma_16816(s, qa[0], b0, b1);
            mma_16816(t, qa[1], b0, b1);
            __half2 p0 = h2exp2(__floats2half2_rn(s[0], s[1]));
            __half2 p1 = h2exp2(__floats2half2_rn(s[2], s[3]));
            __half2 p2 = h2exp2(__floats2half2_rn(t[0], t[1]));
            __half2 p3 = h2exp2(__floats2half2_rn(t[2], t[3]));
            P[0][nt][0] = *(unsigned*)&p0; P[0][nt][1] = *(unsigned*)&p1;
            P[1][nt][0] = *(unsigned*)&p2; P[1][nt][1] = *(unsigned*)&p3;
        }

        // ---- O += P @ Vt (nv=2 tile accumulates l via ones column) ----
#pragma unroll
        for (int kt = 0; kt < 4; kt++) {
            unsigned a0[4] = { P[0][2*kt][0], P[0][2*kt][1],
                               P[0][2*kt+1][0], P[0][2*kt+1][1] };
            unsigned a1[4] = { P[1][2*kt][0], P[1][2*kt][1],
                               P[1][2*kt+1][0], P[1][2*kt+1][1] };
#pragma unroll
            for (int nvt = 0; nvt < 3; nvt++) {
                unsigned b0 = *(const unsigned*)&Vts[buf][nvt * 8 + gr][kt * 16 + 2 * gc];
                unsigned b1 = *(const unsigned*)&Vts[buf][nvt * 8 + gr][kt * 16 + 2 * gc + 8];
                mma_16816(O[0][nvt], a0, b0, b1);
                mma_16816(O[1][nvt], a1, b0, b1);
            }
        }

        __syncthreads();
        if (c + 1 < NCH) {
            *(float4*)&Ksh[buf ^ 1][kr][ko] = nk;
            *(float4*)&Vts[buf ^ 1][vd][vo] = nv;
        }
        __syncthreads();
    }

    // ---- epilogue: normalize by l (column 16) and store ----
    const int b = bh >> 2, h = bh & 3;
#pragma unroll
    for (int mt = 0; mt < 2; mt++) {
        const int srclane = lane & ~3;   // gc==0 lane of this quad holds col 16
        float l_lo = __shfl_sync(0xffffffffu, O[mt][2][0], srclane);
        float l_hi = __shfl_sync(0xffffffffu, O[mt][2][2], srclane);
        const float inv_lo = 1.f / l_lo;
        const float inv_hi = 1.f / l_hi;
        const int r_lo = qrow0 + mt * 16 + gr;
        const int r_hi = r_lo + 8;
#pragma unroll
        for (int nvt = 0; nvt < 2; nvt++) {
            float2 vlo = make_float2(O[mt][nvt][0] * inv_lo, O[mt][nvt][1] * inv_lo);
            float2 vhi = make_float2(O[mt][nvt][2] * inv_hi, O[mt][nvt][3] * inv_hi);
            *(float2*)&g_heads[((size_t)(b * SS) + r_lo) * EMB + h * HEADD + nvt * 8 + 2 * gc] = vlo;
            *(float2*)&g_heads[((size_t)(b * SS) + r_hi) * EMB + h * HEADD + nvt * 8 + 2 * gc] = vhi;
        }
    }
}

// =====================================================================
// Kernel 3: Wo proj + residual + LN1 + FFN(relu) + residual + LN2.
// 2 tokens per loop iteration.
// =====================================================================
__global__ void __launch_bounds__(256) post_kernel(
    const float* __restrict__ data,
    const float* __restrict__ Wo,  const float* __restrict__ bo,
    const float* __restrict__ g1,  const float* __restrict__ bl1,
    const float* __restrict__ W1,  const float* __restrict__ b1,
    const float* __restrict__ W2,  const float* __restrict__ b2,
    const float* __restrict__ g2,  const float* __restrict__ bl2,
    float* __restrict__ out)
{
    __shared__ float Wos[4096];
    __shared__ float W1s[4096];
    __shared__ float W2s[4096];

    const int tid = threadIdx.x;
    for (int i = tid; i < 4096; i += 256) {
        Wos[i] = Wo[i]; W1s[i] = W1[i]; W2s[i] = W2[i];
    }
    __syncthreads();

    const int w    = tid >> 5;
    const int lane = tid & 31;

    const float bo0 = bo[lane],  bo1 = bo[lane + 32];
    const float b10 = b1[lane],  b11 = b1[lane + 32];
    const float b20 = b2[lane],  b21 = b2[lane + 32];
    const float g10 = g1[lane],  g11 = g1[lane + 32];
    const float e10 = bl1[lane], e11 = bl1[lane + 32];
    const float g20 = g2[lane],  g21 = g2[lane + 32];
    const float e20 = bl2[lane], e21 = bl2[lane + 32];

    const int tpw  = NTOK / (gridDim.x * 8);
    const int tok0 = (blockIdx.x * 8 + w) * tpw;

    for (int t = 0; t < tpw; t += 2) {
        const int tokA = tok0 + t;
        const int tokB = tokA + 1;
        float aA0 = g_heads[tokA * 64 + lane];
        float aA1 = g_heads[tokA * 64 + lane + 32];
        float aB0 = g_heads[tokB * 64 + lane];
        float aB1 = g_heads[tokB * 64 + lane + 32];

        float A0 = bo0, A1 = bo1, B0 = bo0, B1 = bo1;
#pragma unroll
        for (int d = 0; d < 32; d++) {
            const float w0 = Wos[d * 64 + lane];
            const float w1 = Wos[d * 64 + lane + 32];
            const float xA = __shfl_sync(0xffffffffu, aA0, d);
            const float xB = __shfl_sync(0xffffffffu, aB0, d);
            A0 = fmaf(xA, w0, A0); A1 = fmaf(xA, w1, A1);
            B0 = fmaf(xB, w0, B0); B1 = fmaf(xB, w1, B1);
        }
#pragma unroll
        for (int d = 32; d < 64; d++) {
            const float w0 = Wos[d * 64 + lane];
            const float w1 = Wos[d * 64 + lane + 32];
            const float xA = __shfl_sync(0xffffffffu, aA1, d - 32);
            const float xB = __shfl_sync(0xffffffffu, aB1, d - 32);
            A0 = fmaf(xA, w0, A0); A1 = fmaf(xA, w1, A1);
            B0 = fmaf(xB, w0, B0); B1 = fmaf(xB, w1, B1);
        }

        float rA0 = data[tokA * 64 + lane]      + A0;
        float rA1 = data[tokA * 64 + lane + 32] + A1;
        float rB0 = data[tokB * 64 + lane]      + B0;
        float rB1 = data[tokB * 64 + lane + 32] + B1;

        float meanA = warp_sum(rA0 + rA1) * (1.f / 64.f);
        float meanB = warp_sum(rB0 + rB1) * (1.f / 64.f);
        float dA0 = rA0 - meanA, dA1 = rA1 - meanA;
        float dB0 = rB0 - meanB, dB1 = rB1 - meanB;
        float varA = warp_sum(dA0 * dA0 + dA1 * dA1) * (1.f / 64.f);
        float varB = warp_sum(dB0 * dB0 + dB1 * dB1) * (1.f / 64.f);
        float ivA = rsqrtf(varA + EPS);
        float ivB = rsqrtf(varB + EPS);
        const float xA10 = dA0 * ivA * g10 + e10;
        const float xA11 = dA1 * ivA * g11 + e11;
        const float xB10 = dB0 * ivB * g10 + e10;
        const float xB11 = dB1 * ivB * g11 + e11;

        A0 = b10; A1 = b11; B0 = b10; B1 = b11;
#pragma unroll
        for (int d = 0; d < 32; d++) {
            const float w0 = W1s[d * 64 + lane];
            const float w1 = W1s[d * 64 + lane + 32];
            const float xA = __shfl_sync(0xffffffffu, xA10, d);
            const float xB = __shfl_sync(0xffffffffu, xB10, d);
            A0 = fmaf(xA, w0, A0); A1 = fmaf(xA, w1, A1);
            B0 = fmaf(xB, w0, B0); B1 = fmaf(xB, w1, B1);
        }
#pragma unroll
        for (int d = 32; d < 64; d++) {
            const float w0 = W1s[d * 64 + lane];
            const float w1 = W1s[d * 64 + lane + 32];
            const float xA = __shfl_sync(0xffffffffu, xA11, d - 32);
            const float xB = __shfl_sync(0xffffffffu, xB11, d - 32);
            A0 = fmaf(xA, w0, A0); A1 = fmaf(xA, w1, A1);
            B0 = fmaf(xB, w0, B0); B1 = fmaf(xB, w1, B1);
        }
        const float hA0 = fmaxf(A0, 0.f), hA1 = fmaxf(A1, 0.f);
        const float hB0 = fmaxf(B0, 0.f), hB1 = fmaxf(B1, 0.f);

        A0 = b20; A1 = b21; B0 = b20; B1 = b21;
#pragma unroll
        for (int d = 0; d < 32; d++) {
            const float w0 = W2s[d * 64 + lane];
            const float w1 = W2s[d * 64 + lane + 32];
            const float xA = __shfl_sync(0xffffffffu, hA0, d);
            const float xB = __shfl_sync(0xffffffffu, hB0, d);
            A0 = fmaf(xA, w0, A0); A1 = fmaf(xA, w1, A1);
            B0 = fmaf(xB, w0, B0); B1 = fmaf(xB, w1, B1);
        }
#pragma unroll
        for (int d = 32; d < 64; d++) {
            const float w0 = W2s[d * 64 + lane];
            const float w1 = W2s[d * 64 + lane + 32];
            const float xA = __shfl_sync(0xffffffffu, hA1, d - 32);
            const float xB = __shfl_sync(0xffffffffu, hB1, d - 32);
            A0 = fmaf(xA, w0, A0); A1 = fmaf(xA, w1, A1);
            B0 = fmaf(xB, w0, B0); B1 = fmaf(xB, w1, B1);
        }

        rA0 = A0 + xA10; rA1 = A1 + xA11;
        rB0 = B0 + xB10; rB1 = B1 + xB11;

        meanA = warp_sum(rA0 + rA1) * (1.f / 64.f);
        meanB = warp_sum(rB0 + rB1) * (1.f / 64.f);
        dA0 = rA0 - meanA; dA1 = rA1 - meanA;
        dB0 = rB0 - meanB; dB1 = rB1 - meanB;
        varA = warp_sum(dA0 * dA0 + dA1 * dA1) * (1.f / 64.f);
        varB = warp_sum(dB0 * dB0 + dB1 * dB1) * (1.f / 64.f);
        ivA = rsqrtf(varA + EPS);
        ivB = rsqrtf(varB + EPS);

        out[tokA * 64 + lane]      = dA0 * ivA * g20 + e20;
        out[tokA * 64 + lane + 32] = dA1 * ivA * g21 + e21;
        out[tokB * 64 + lane]      = dB0 * ivB * g20 + e20;
        out[tokB * 64 + lane + 32] = dB1 * ivB * g21 + e21;
    }
}

// =====================================================================
extern "C" void kernel_launch(void* const* d_in, const int* in_sizes, int n_in,
                              void* d_out, int out_size)
{
    const float* data  = (const float*)d_in[0];
    const float* Wq    = (const float*)d_in[1];
    const float* Wk    = (const float*)d_in[2];
    const float* Wv    = (const float*)d_in[3];
    const float* Wo    = (const float*)d_in[4];
    const float* bo    = (const float*)d_in[5];
    const float* ln1_g = (const float*)d_in[6];
    const float* ln1_b = (const float*)d_in[7];
    const float* W1    = (const float*)d_in[8];
    const float* b1    = (const float*)d_in[9];
    const float* W2    = (const float*)d_in[10];
    const float* b2    = (const float*)d_in[11];
    const float* ln2_g = (const float*)d_in[12];
    const float* ln2_b = (const float*)d_in[13];
    float* out = (float*)d_out;

    prep_kernel<<<48, 256>>>(Wq, Wk, Wv);
    qkv_kernel<<<256, 128>>>(data);
    attn_kernel<<<dim3(NHEAD * BB, SS / 128), 128>>>();
    post_kernel<<<512, 256>>>(data, Wo, bo, ln1_g, ln1_b, W1, b1,
                              W2, b2, ln2_g, ln2_b, out);
}

// round 9
// speedup vs baseline: 5.2330x; 1.3083x over previous
#include <cuda_runtime.h>
#include <cuda_fp16.h>
#include <math.h>

#define EMB    64
#define NHEAD  4
#define HEADD  16
#define BB     8
#define SS     2048
#define NTOK   (BB*SS)            // 16384
#define EPS    1e-5f
// exp2-domain scale: 1/sqrt(16) * log2(e)
#define QSCALE (0.25f * 1.44269504088896f)

#define BK     64                 // keys per chunk
#define NCH    (SS/BK)            // 32

// ---------------- device scratch (no allocations allowed) ----------------
__device__ __align__(16) __half g_Qh[NTOK*EMB];   // [bh][s][16], QSCALE folded in
__device__ __align__(16) __half g_Kh[NTOK*EMB];   // [bh][s][16]
__device__ __align__(16) __half g_Vt[NTOK*EMB];   // [bh][16][s]  (transposed!)
__device__ __align__(16) float  g_heads[NTOK*EMB];  // concat layout [b][s][h*16+k]
__device__ __align__(16) __half g_Wth[192*72];    // QKV weights [n][k]
__device__ __align__(16) __half g_Wpost[3*64*72]; // Wo|W1|W2 [n][k]

__device__ __forceinline__ void mma_16816(float* d, const unsigned* a,
                                          unsigned b0, unsigned b1) {
    asm volatile(
        "mma.sync.aligned.m16n8k16.row.col.f32.f16.f16.f32 "
        "{%0,%1,%2,%3}, {%4,%5,%6,%7}, {%8,%9}, {%0,%1,%2,%3};\n"
        : "+f"(d[0]), "+f"(d[1]), "+f"(d[2]), "+f"(d[3])
        : "r"(a[0]), "r"(a[1]), "r"(a[2]), "r"(a[3]), "r"(b0), "r"(b1));
}

__device__ __forceinline__ unsigned packh2(float x, float y) {
    __half2 h = __floats2half2_rn(x, y);
    return *(unsigned*)&h;
}

// =====================================================================
// Kernel 0: one-time weight conversion to fp16 B-fragment layouts.
// =====================================================================
__global__ void prep_kernel(const float* __restrict__ Wq,
                            const float* __restrict__ Wk,
                            const float* __restrict__ Wv,
                            const float* __restrict__ Wo,
                            const float* __restrict__ W1,
                            const float* __restrict__ W2)
{
    const int i = blockIdx.x * 256 + threadIdx.x;
    if (i < 192 * 64) {
        const int n = i % 192, k = i / 192;
        float w;
        if (n < 64)        w = Wq[(n >> 4) * 1024 + k * 16 + (n & 15)] * QSCALE;
        else if (n < 128)  w = Wk[((n - 64) >> 4) * 1024 + k * 16 + ((n - 64) & 15)];
        else               w = Wv[((n - 128) >> 4) * 1024 + k * 16 + ((n - 128) & 15)];
        g_Wth[n * 72 + k] = __float2half_rn(w);
    } else if (i < 192 * 64 + 3 * 64 * 64) {
        const int j = i - 192 * 64;
        const int m = j >> 12;          // 0 Wo, 1 W1, 2 W2
        const int r = j & 4095;
        const int n = r & 63, k = r >> 6;
        const float* W = (m == 0) ? Wo : (m == 1) ? W1 : W2;
        g_Wpost[(m * 64 + n) * 72 + k] = __float2half_rn(W[k * 64 + n]);
    }
}

// =====================================================================
// Kernel 1: QKV projection on tensor cores.
// =====================================================================
__global__ void __launch_bounds__(128) qkv_kernel(const float* __restrict__ data)
{
    __shared__ __align__(16) __half Wt[192 * 72];     // 27648 B
    __shared__ __align__(16) __half stage_v[64 * 66]; // 8448 B

    const int tid  = threadIdx.x;
    const int warp = tid >> 5;
    const int lane = tid & 31;
    const int gr   = lane >> 2;
    const int gc   = lane & 3;

    {
        const uint4* src = (const uint4*)g_Wth;
        uint4* dst = (uint4*)Wt;
        for (int i = tid; i < 1728; i += 128) dst[i] = src[i];
    }
    __syncthreads();

    const int tile = blockIdx.x * 4 + warp;
    const int tok0 = tile * 16;

    unsigned a[4][4];
#pragma unroll
    for (int kt = 0; kt < 4; kt++) {
        const float* r0 = data + (size_t)(tok0 + gr) * 64 + kt * 16 + 2 * gc;
        const float* r8 = r0 + 8 * 64;
        float2 x0 = *(const float2*)r0;
        float2 x8 = *(const float2*)r8;
        float2 y0 = *(const float2*)(r0 + 8);
        float2 y8 = *(const float2*)(r8 + 8);
        a[kt][0] = packh2(x0.x, x0.y); a[kt][1] = packh2(x8.x, x8.y);
        a[kt][2] = packh2(y0.x, y0.y); a[kt][3] = packh2(y8.x, y8.y);
    }

    float acc[24][4] = {};
#pragma unroll
    for (int nt = 0; nt < 24; nt++) {
#pragma unroll
        for (int kt = 0; kt < 4; kt++) {
            const __half* base = &Wt[(nt * 8 + gr) * 72 + kt * 16 + 2 * gc];
            unsigned b0 = *(const unsigned*)base;
            unsigned b1 = *(const unsigned*)(base + 8);
            mma_16816(acc[nt], a[kt], b0, b1);
        }
    }

#pragma unroll
    for (int nt = 0; nt < 8; nt++) {
        const int vcol = nt * 8 + 2 * gc;
        *(__half2*)&stage_v[(warp * 16 + gr)     * 66 + vcol] =
            __floats2half2_rn(acc[16 + nt][0], acc[16 + nt][1]);
        *(__half2*)&stage_v[(warp * 16 + gr + 8) * 66 + vcol] =
            __floats2half2_rn(acc[16 + nt][2], acc[16 + nt][3]);
    }
    __syncthreads();

    const int b  = tok0 >> 11;
    const int sb = tok0 & 2047;
#pragma unroll
    for (int nt = 0; nt < 8; nt++) {           // Q
        const int head = nt >> 1;
        const int kk0  = (nt & 1) * 8 + 2 * gc;
        const size_t base = (size_t)(b * 4 + head) * 2048;
        *(__half2*)&g_Qh[(base + sb + gr)     * 16 + kk0] = __floats2half2_rn(acc[nt][0], acc[nt][1]);
        *(__half2*)&g_Qh[(base + sb + gr + 8) * 16 + kk0] = __floats2half2_rn(acc[nt][2], acc[nt][3]);
    }
#pragma unroll
    for (int nt = 0; nt < 8; nt++) {           // K
        const int head = nt >> 1;
        const int kk0  = (nt & 1) * 8 + 2 * gc;
        const size_t base = (size_t)(b * 4 + head) * 2048;
        *(__half2*)&g_Kh[(base + sb + gr)     * 16 + kk0] = __floats2half2_rn(acc[8 + nt][0], acc[8 + nt][1]);
        *(__half2*)&g_Kh[(base + sb + gr + 8) * 16 + kk0] = __floats2half2_rn(acc[8 + nt][2], acc[8 + nt][3]);
    }

    const int s0 = (blockIdx.x * 64) & 2047;
    const int bb = (blockIdx.x * 64) >> 11;
#pragma unroll
    for (int q = 0; q < 4; q++) {
        const int idx = q * 128 + tid;
        const int c   = idx >> 3;
        const int j   = idx & 7;
        const int h   = c >> 4;
        const int kk  = c & 15;
        __half2 p0 = __halves2half2(stage_v[(8*j+0)*66+c], stage_v[(8*j+1)*66+c]);
        __half2 p1 = __halves2half2(stage_v[(8*j+2)*66+c], stage_v[(8*j+3)*66+c]);
        __half2 p2 = __halves2half2(stage_v[(8*j+4)*66+c], stage_v[(8*j+5)*66+c]);
        __half2 p3 = __halves2half2(stage_v[(8*j+6)*66+c], stage_v[(8*j+7)*66+c]);
        uint4 u;
        u.x = *(unsigned*)&p0; u.y = *(unsigned*)&p1;
        u.z = *(unsigned*)&p2; u.w = *(unsigned*)&p3;
        *(uint4*)&g_Vt[((size_t)(bb * 4 + h) * 16 + kk) * 2048 + s0 + 8 * j] = u;
    }
}

// =====================================================================
// Kernel 2: fp16 tensor-core flash attention (no-max softmax).
// =====================================================================
__global__ void __launch_bounds__(128) attn_kernel()
{
    __shared__ __align__(16) __half Ksh[2][BK][24];
    __shared__ __align__(16) __half Vts[2][24][72];

    const int bh   = blockIdx.x;
    const int tid  = threadIdx.x;
    const int warp = tid >> 5;
    const int lane = tid & 31;
    const int gr   = lane >> 2;
    const int gc   = lane & 3;
    const int qrow0 = blockIdx.y * 128 + warp * 32;

    for (int i = tid; i < 2 * 8 * 72; i += 128) {
        int bufi = i / (8 * 72);
        int rem  = i % (8 * 72);
        int r = rem / 72, cc = rem % 72;
        Vts[bufi][16 + r][cc] = __float2half(r == 0 ? 1.0f : 0.0f);
    }

    const __half* Qbh = g_Qh + (size_t)bh * SS * HEADD;
    unsigned qa[2][4];
#pragma unroll
    for (int mt = 0; mt < 2; mt++) {
        const __half* r0 = Qbh + (size_t)(qrow0 + mt * 16 + gr) * HEADD;
        qa[mt][0] = *(const unsigned*)(r0 + 2 * gc);
        qa[mt][1] = *(const unsigned*)(r0 + 8 * HEADD + 2 * gc);
        qa[mt][2] = *(const unsigned*)(r0 + 2 * gc + 8);
        qa[mt][3] = *(const unsigned*)(r0 + 8 * HEADD + 2 * gc + 8);
    }

    const __half* Kbh = g_Kh + (size_t)bh * SS * HEADD;
    const __half* Vbh = g_Vt + (size_t)bh * HEADD * SS;

    const int kr = tid >> 1, ko = (tid & 1) * 8;
    const int vd = tid >> 3, vo = (tid & 7) * 8;

    float4 nk = *(const float4*)(Kbh + (size_t)kr * HEADD + ko);
    float4 nv = *(const float4*)(Vbh + (size_t)vd * SS + vo);
    *(float4*)&Ksh[0][kr][ko] = nk;
    *(float4*)&Vts[0][vd][vo] = nv;
    __syncthreads();

    float O[2][3][4] = {};
    unsigned P[2][8][2];

    for (int c = 0; c < NCH; c++) {
        const int buf = c & 1;
        if (c + 1 < NCH) {
            nk = *(const float4*)(Kbh + (size_t)((c + 1) * BK + kr) * HEADD + ko);
            nv = *(const float4*)(Vbh + (size_t)vd * SS + (c + 1) * BK + vo);
        }

#pragma unroll
        for (int nt = 0; nt < 8; nt++) {
            unsigned b0 = *(const unsigned*)&Ksh[buf][nt * 8 + gr][2 * gc];
            unsigned b1 = *(const unsigned*)&Ksh[buf][nt * 8 + gr][2 * gc + 8];
            float s[4] = {0.f, 0.f, 0.f, 0.f};
            float t[4] = {0.f, 0.f, 0.f, 0.f};
            mma_16816(s, qa[0], b0, b1);
            mma_16816(t, qa[1], b0, b1);
            __half2 p0 = h2exp2(__floats2half2_rn(s[0], s[1]));
            __half2 p1 = h2exp2(__floats2half2_rn(s[2], s[3]));
            __half2 p2 = h2exp2(__floats2half2_rn(t[0], t[1]));
            __half2 p3 = h2exp2(__floats2half2_rn(t[2], t[3]));
            P[0][nt][0] = *(unsigned*)&p0; P[0][nt][1] = *(unsigned*)&p1;
            P[1][nt][0] = *(unsigned*)&p2; P[1][nt][1] = *(unsigned*)&p3;
        }

#pragma unroll
        for (int kt = 0; kt < 4; kt++) {
            unsigned a0[4] = { P[0][2*kt][0], P[0][2*kt][1],
                               P[0][2*kt+1][0], P[0][2*kt+1][1] };
            unsigned a1[4] = { P[1][2*kt][0], P[1][2*kt][1],
                               P[1][2*kt+1][0], P[1][2*kt+1][1] };
#pragma unroll
            for (int nvt = 0; nvt < 3; nvt++) {
                unsigned b0 = *(const unsigned*)&Vts[buf][nvt * 8 + gr][kt * 16 + 2 * gc];
                unsigned b1 = *(const unsigned*)&Vts[buf][nvt * 8 + gr][kt * 16 + 2 * gc + 8];
                mma_16816(O[0][nvt], a0, b0, b1);
                mma_16816(O[1][nvt], a1, b0, b1);
            }
        }

        __syncthreads();
        if (c + 1 < NCH) {
            *(float4*)&Ksh[buf ^ 1][kr][ko] = nk;
            *(float4*)&Vts[buf ^ 1][vd][vo] = nv;
        }
        __syncthreads();
    }

    const int b = bh >> 2, h = bh & 3;
#pragma unroll
    for (int mt = 0; mt < 2; mt++) {
        const int srclane = lane & ~3;
        float l_lo = __shfl_sync(0xffffffffu, O[mt][2][0], srclane);
        float l_hi = __shfl_sync(0xffffffffu, O[mt][2][2], srclane);
        const float inv_lo = 1.f / l_lo;
        const float inv_hi = 1.f / l_hi;
        const int r_lo = qrow0 + mt * 16 + gr;
        const int r_hi = r_lo + 8;
#pragma unroll
        for (int nvt = 0; nvt < 2; nvt++) {
            float2 vlo = make_float2(O[mt][nvt][0] * inv_lo, O[mt][nvt][1] * inv_lo);
            float2 vhi = make_float2(O[mt][nvt][2] * inv_hi, O[mt][nvt][3] * inv_hi);
            *(float2*)&g_heads[((size_t)(b * SS) + r_lo) * EMB + h * HEADD + nvt * 8 + 2 * gc] = vlo;
            *(float2*)&g_heads[((size_t)(b * SS) + r_hi) * EMB + h * HEADD + nvt * 8 + 2 * gc] = vhi;
        }
    }
}

// =====================================================================
// Kernel 3: post block on tensor cores.
// Warp = 16 tokens. GEMM(Wo) -> +res +bo -> LN1 -> GEMM(W1) -> relu ->
// GEMM(W2) -> +b2 +x1 -> LN2 -> out.  C-frag layout == next A-frag layout.
// =====================================================================
__global__ void __launch_bounds__(128) post_kernel(
    const float* __restrict__ data,
    const float* __restrict__ bo,
    const float* __restrict__ g1,  const float* __restrict__ bl1,
    const float* __restrict__ b1,  const float* __restrict__ b2,
    const float* __restrict__ g2,  const float* __restrict__ bl2,
    float* __restrict__ out)
{
    __shared__ __align__(16) __half Wsh[3 * 64 * 72];   // 27648 B

    const int tid  = threadIdx.x;
    const int warp = tid >> 5;
    const int lane = tid & 31;
    const int gr   = lane >> 2;
    const int gc   = lane & 3;

    {
        const uint4* src = (const uint4*)g_Wpost;
        uint4* dst = (uint4*)Wsh;
        for (int i = tid; i < 1728; i += 128) dst[i] = src[i];
    }
    __syncthreads();

    const int tile = blockIdx.x * 4 + warp;
    const int tok0 = tile * 16;
    const float* rowL = data + (size_t)(tok0 + gr) * 64;
    const float* rowH = rowL + 8 * 64;

    // A fragments from g_heads
    unsigned a[4][4];
#pragma unroll
    for (int kt = 0; kt < 4; kt++) {
        const float* r0 = g_heads + (size_t)(tok0 + gr) * 64 + kt * 16 + 2 * gc;
        const float* r8 = r0 + 8 * 64;
        float2 x0 = *(const float2*)r0;
        float2 x8 = *(const float2*)r8;
        float2 y0 = *(const float2*)(r0 + 8);
        float2 y8 = *(const float2*)(r8 + 8);
        a[kt][0] = packh2(x0.x, x0.y); a[kt][1] = packh2(x8.x, x8.y);
        a[kt][2] = packh2(y0.x, y0.y); a[kt][3] = packh2(y8.x, y8.y);
    }

    // ---- GEMM1: heads @ Wo ----
    float acc[8][4] = {};
#pragma unroll
    for (int nt = 0; nt < 8; nt++)
#pragma unroll
        for (int kt = 0; kt < 4; kt++) {
            const __half* base = &Wsh[(nt * 8 + gr) * 72 + kt * 16 + 2 * gc];
            mma_16816(acc[nt], a[kt], *(const unsigned*)base, *(const unsigned*)(base + 8));
        }

    // ---- + residual + bo, LN1 ----
    float x1[8][4];
    float sl = 0.f, sh = 0.f;
#pragma unroll
    for (int nt = 0; nt < 8; nt++) {
        const int col = nt * 8 + 2 * gc;
        float2 dl = *(const float2*)(rowL + col);
        float2 dh = *(const float2*)(rowH + col);
        float2 bb = *(const float2*)(bo + col);
        x1[nt][0] = acc[nt][0] + dl.x + bb.x;
        x1[nt][1] = acc[nt][1] + dl.y + bb.y;
        x1[nt][2] = acc[nt][2] + dh.x + bb.x;
        x1[nt][3] = acc[nt][3] + dh.y + bb.y;
        sl += x1[nt][0] + x1[nt][1];
        sh += x1[nt][2] + x1[nt][3];
    }
    sl += __shfl_xor_sync(0xffffffffu, sl, 1); sl += __shfl_xor_sync(0xffffffffu, sl, 2);
    sh += __shfl_xor_sync(0xffffffffu, sh, 1); sh += __shfl_xor_sync(0xffffffffu, sh, 2);
    float ml = sl * (1.f / 64.f), mh = sh * (1.f / 64.f);
    float vl = 0.f, vh = 0.f;
#pragma unroll
    for (int nt = 0; nt < 8; nt++) {
        x1[nt][0] -= ml; x1[nt][1] -= ml; x1[nt][2] -= mh; x1[nt][3] -= mh;
        vl += x1[nt][0]*x1[nt][0] + x1[nt][1]*x1[nt][1];
        vh += x1[nt][2]*x1[nt][2] + x1[nt][3]*x1[nt][3];
    }
    vl += __shfl_xor_sync(0xffffffffu, vl, 1); vl += __shfl_xor_sync(0xffffffffu, vl, 2);
    vh += __shfl_xor_sync(0xffffffffu, vh, 1); vh += __shfl_xor_sync(0xffffffffu, vh, 2);
    float il = rsqrtf(vl * (1.f / 64.f) + EPS);
    float ih = rsqrtf(vh * (1.f / 64.f) + EPS);
#pragma unroll
    for (int nt = 0; nt < 8; nt++) {
        const int col = nt * 8 + 2 * gc;
        float2 gg = *(const float2*)(g1 + col);
        float2 ee = *(const float2*)(bl1 + col);
        x1[nt][0] = x1[nt][0] * il * gg.x + ee.x;
        x1[nt][1] = x1[nt][1] * il * gg.y + ee.y;
        x1[nt][2] = x1[nt][2] * ih * gg.x + ee.x;
        x1[nt][3] = x1[nt][3] * ih * gg.y + ee.y;
    }

    // ---- GEMM2: x1 @ W1 (C-frag -> A-frag, no shuffles) ----
#pragma unroll
    for (int kt = 0; kt < 4; kt++) {
        a[kt][0] = packh2(x1[2*kt][0],   x1[2*kt][1]);
        a[kt][1] = packh2(x1[2*kt][2],   x1[2*kt][3]);
        a[kt][2] = packh2(x1[2*kt+1][0], x1[2*kt+1][1]);
        a[kt][3] = packh2(x1[2*kt+1][2], x1[2*kt+1][3]);
    }
    float acc2[8][4] = {};
#pragma unroll
    for (int nt = 0; nt < 8; nt++)
#pragma unroll
        for (int kt = 0; kt < 4; kt++) {
            const __half* base = &Wsh[(64 + nt * 8 + gr) * 72 + kt * 16 + 2 * gc];
            mma_16816(acc2[nt], a[kt], *(const unsigned*)base, *(const unsigned*)(base + 8));
        }

    // relu(+b1) -> A fragments
#pragma unroll
    for (int nt = 0; nt < 8; nt++) {
        const int col = nt * 8 + 2 * gc;
        float2 bb = *(const float2*)(b1 + col);
        acc2[nt][0] = fmaxf(acc2[nt][0] + bb.x, 0.f);
        acc2[nt][1] = fmaxf(acc2[nt][1] + bb.y, 0.f);
        acc2[nt][2] = fmaxf(acc2[nt][2] + bb.x, 0.f);
        acc2[nt][3] = fmaxf(acc2[nt][3] + bb.y, 0.f);
    }
#pragma unroll
    for (int kt = 0; kt < 4; kt++) {
        a[kt][0] = packh2(acc2[2*kt][0],   acc2[2*kt][1]);
        a[kt][1] = packh2(acc2[2*kt][2],   acc2[2*kt][3]);
        a[kt][2] = packh2(acc2[2*kt+1][0], acc2[2*kt+1][1]);
        a[kt][3] = packh2(acc2[2*kt+1][2], acc2[2*kt+1][3]);
    }

    // ---- GEMM3: h @ W2 ----
    float acc3[8][4] = {};
#pragma unroll
    for (int nt = 0; nt < 8; nt++)
#pragma unroll
        for (int kt = 0; kt < 4; kt++) {
            const __half* base = &Wsh[(128 + nt * 8 + gr) * 72 + kt * 16 + 2 * gc];
            mma_16816(acc3[nt], a[kt], *(const unsigned*)base, *(const unsigned*)(base + 8));
        }

    // ---- + b2 + x1, LN2, store ----
    sl = 0.f; sh = 0.f;
#pragma unroll
    for (int nt = 0; nt < 8; nt++) {
        const int col = nt * 8 + 2 * gc;
        float2 bb = *(const float2*)(b2 + col);
        acc3[nt][0] += bb.x + x1[nt][0];
        acc3[nt][1] += bb.y + x1[nt][1];
        acc3[nt][2] += bb.x + x1[nt][2];
        acc3[nt][3] += bb.y + x1[nt][3];
        sl += acc3[nt][0] + acc3[nt][1];
        sh += acc3[nt][2] + acc3[nt][3];
    }
    sl += __shfl_xor_sync(0xffffffffu, sl, 1); sl += __shfl_xor_sync(0xffffffffu, sl, 2);
    sh += __shfl_xor_sync(0xffffffffu, sh, 1); sh += __shfl_xor_sync(0xffffffffu, sh, 2);
    ml = sl * (1.f / 64.f); mh = sh * (1.f / 64.f);
    vl = 0.f; vh = 0.f;
#pragma unroll
    for (int nt = 0; nt < 8; nt++) {
        acc3[nt][0] -= ml; acc3[nt][1] -= ml; acc3[nt][2] -= mh; acc3[nt][3] -= mh;
        vl += acc3[nt][0]*acc3[nt][0] + acc3[nt][1]*acc3[nt][1];
        vh += acc3[nt][2]*acc3[nt][2] + acc3[nt][3]*acc3[nt][3];
    }
    vl += __shfl_xor_sync(0xffffffffu, vl, 1); vl += __shfl_xor_sync(0xffffffffu, vl, 2);
    vh += __shfl_xor_sync(0xffffffffu, vh, 1); vh += __shfl_xor_sync(0xffffffffu, vh, 2);
    il = rsqrtf(vl * (1.f / 64.f) + EPS);
    ih = rsqrtf(vh * (1.f / 64.f) + EPS);

    float* outL = out + (size_t)(tok0 + gr) * 64;
    float* outH = outL + 8 * 64;
#pragma unroll
    for (int nt = 0; nt < 8; nt++) {
        const int col = nt * 8 + 2 * gc;
        float2 gg = *(const float2*)(g2 + col);
        float2 ee = *(const float2*)(bl2 + col);
        *(float2*)(outL + col) = make_float2(acc3[nt][0] * il * gg.x + ee.x,
                                             acc3[nt][1] * il * gg.y + ee.y);
        *(float2*)(outH + col) = make_float2(acc3[nt][2] * ih * gg.x + ee.x,
                                             acc3[nt][3] * ih * gg.y + ee.y);
    }
}

// =====================================================================
extern "C" void kernel_launch(void* const* d_in, const int* in_sizes, int n_in,
                              void* d_out, int out_size)
{
    const float* data  = (const float*)d_in[0];
    const float* Wq    = (const float*)d_in[1];
    const float* Wk    = (const float*)d_in[2];
    const float* Wv    = (const float*)d_in[3];
    const float* Wo    = (const float*)d_in[4];
    const float* bo    = (const float*)d_in[5];
    const float* ln1_g = (const float*)d_in[6];
    const float* ln1_b = (const float*)d_in[7];
    const float* W1    = (const float*)d_in[8];
    const float* b1    = (const float*)d_in[9];
    const float* W2    = (const float*)d_in[10];
    const float* b2    = (const float*)d_in[11];
    const float* ln2_g = (const float*)d_in[12];
    const float* ln2_b = (const float*)d_in[13];
    float* out = (float*)d_out;

    prep_kernel<<<96, 256>>>(Wq, Wk, Wv, Wo, W1, W2);
    qkv_kernel<<<256, 128>>>(data);
    attn_kernel<<<dim3(NHEAD * BB, SS / 128), 128>>>();
    post_kernel<<<256, 128>>>(data, bo, ln1_g, ln1_b, b1, b2, ln2_g, ln2_b, out);
}

// round 10
// speedup vs baseline: 5.5268x; 1.0561x over previous
#include <cuda_runtime.h>
#include <cuda_fp16.h>
#include <math.h>

#define EMB    64
#define NHEAD  4
#define HEADD  16
#define BB     8
#define SS     2048
#define NTOK   (BB*SS)            // 16384
#define EPS    1e-5f
// exp2-domain scale: 1/sqrt(16) * log2(e)
#define QSCALE (0.25f * 1.44269504088896f)

#define BK     64                 // keys per chunk
#define NCH    (SS/BK)            // 32

// ---------------- device scratch (no allocations allowed) ----------------
__device__ __align__(16) __half g_Qh[NTOK*EMB];   // [bh][s][16], QSCALE folded in
__device__ __align__(16) __half g_Kh[NTOK*EMB];   // [bh][s][16]
__device__ __align__(16) __half g_Vt[NTOK*EMB];   // [bh][16][s]  (transposed!)
__device__ __align__(16) float  g_heads[NTOK*EMB];  // concat layout [b][s][h*16+k]
__device__ __align__(16) __half g_Wth[192*72];    // QKV weights [n][k]
__device__ __align__(16) __half g_Wpost[3*64*72]; // Wo|W1|W2 [n][k]

__device__ __forceinline__ void mma_16816(float* d, const unsigned* a,
                                          unsigned b0, unsigned b1) {
    asm volatile(
        "mma.sync.aligned.m16n8k16.row.col.f32.f16.f16.f32 "
        "{%0,%1,%2,%3}, {%4,%5,%6,%7}, {%8,%9}, {%0,%1,%2,%3};\n"
        : "+f"(d[0]), "+f"(d[1]), "+f"(d[2]), "+f"(d[3])
        : "r"(a[0]), "r"(a[1]), "r"(a[2]), "r"(a[3]), "r"(b0), "r"(b1));
}

__device__ __forceinline__ unsigned packh2(float x, float y) {
    __half2 h = __floats2half2_rn(x, y);
    return *(unsigned*)&h;
}

// =====================================================================
// Kernel 0: one-time weight conversion to fp16 B-fragment layouts.
// =====================================================================
__global__ void prep_kernel(const float* __restrict__ Wq,
                            const float* __restrict__ Wk,
                            const float* __restrict__ Wv,
                            const float* __restrict__ Wo,
                            const float* __restrict__ W1,
                            const float* __restrict__ W2)
{
    const int i = blockIdx.x * 256 + threadIdx.x;
    if (i < 192 * 64) {
        const int n = i % 192, k = i / 192;
        float w;
        if (n < 64)        w = Wq[(n >> 4) * 1024 + k * 16 + (n & 15)] * QSCALE;
        else if (n < 128)  w = Wk[((n - 64) >> 4) * 1024 + k * 16 + ((n - 64) & 15)];
        else               w = Wv[((n - 128) >> 4) * 1024 + k * 16 + ((n - 128) & 15)];
        g_Wth[n * 72 + k] = __float2half_rn(w);
    } else if (i < 192 * 64 + 3 * 64 * 64) {
        const int j = i - 192 * 64;
        const int m = j >> 12;          // 0 Wo, 1 W1, 2 W2
        const int r = j & 4095;
        const int n = r & 63, k = r >> 6;
        const float* W = (m == 0) ? Wo : (m == 1) ? W1 : W2;
        g_Wpost[(m * 64 + n) * 72 + k] = __float2half_rn(W[k * 64 + n]);
    }
}

// =====================================================================
// Kernel 1: QKV projection on tensor cores. B-frags direct from L1/L2.
// =====================================================================
__global__ void __launch_bounds__(128) qkv_kernel(const float* __restrict__ data)
{
    __shared__ __align__(16) __half stage_v[64 * 66]; // 8448 B

    const int tid  = threadIdx.x;
    const int warp = tid >> 5;
    const int lane = tid & 31;
    const int gr   = lane >> 2;
    const int gc   = lane & 3;

    const int tile = blockIdx.x * 4 + warp;
    const int tok0 = tile * 16;

    unsigned a[4][4];
#pragma unroll
    for (int kt = 0; kt < 4; kt++) {
        const float* r0 = data + (size_t)(tok0 + gr) * 64 + kt * 16 + 2 * gc;
        const float* r8 = r0 + 8 * 64;
        float2 x0 = *(const float2*)r0;
        float2 x8 = *(const float2*)r8;
        float2 y0 = *(const float2*)(r0 + 8);
        float2 y8 = *(const float2*)(r8 + 8);
        a[kt][0] = packh2(x0.x, x0.y); a[kt][1] = packh2(x8.x, x8.y);
        a[kt][2] = packh2(y0.x, y0.y); a[kt][3] = packh2(y8.x, y8.y);
    }

    float acc[24][4] = {};
#pragma unroll
    for (int nt = 0; nt < 24; nt++) {
#pragma unroll
        for (int kt = 0; kt < 4; kt++) {
            const __half* base = &g_Wth[(nt * 8 + gr) * 72 + kt * 16 + 2 * gc];
            unsigned b0 = *(const unsigned*)base;
            unsigned b1 = *(const unsigned*)(base + 8);
            mma_16816(acc[nt], a[kt], b0, b1);
        }
    }

#pragma unroll
    for (int nt = 0; nt < 8; nt++) {
        const int vcol = nt * 8 + 2 * gc;
        *(__half2*)&stage_v[(warp * 16 + gr)     * 66 + vcol] =
            __floats2half2_rn(acc[16 + nt][0], acc[16 + nt][1]);
        *(__half2*)&stage_v[(warp * 16 + gr + 8) * 66 + vcol] =
            __floats2half2_rn(acc[16 + nt][2], acc[16 + nt][3]);
    }
    __syncthreads();

    const int b  = tok0 >> 11;
    const int sb = tok0 & 2047;
#pragma unroll
    for (int nt = 0; nt < 8; nt++) {           // Q
        const int head = nt >> 1;
        const int kk0  = (nt & 1) * 8 + 2 * gc;
        const size_t base = (size_t)(b * 4 + head) * 2048;
        *(__half2*)&g_Qh[(base + sb + gr)     * 16 + kk0] = __floats2half2_rn(acc[nt][0], acc[nt][1]);
        *(__half2*)&g_Qh[(base + sb + gr + 8) * 16 + kk0] = __floats2half2_rn(acc[nt][2], acc[nt][3]);
    }
#pragma unroll
    for (int nt = 0; nt < 8; nt++) {           // K
        const int head = nt >> 1;
        const int kk0  = (nt & 1) * 8 + 2 * gc;
        const size_t base = (size_t)(b * 4 + head) * 2048;
        *(__half2*)&g_Kh[(base + sb + gr)     * 16 + kk0] = __floats2half2_rn(acc[8 + nt][0], acc[8 + nt][1]);
        *(__half2*)&g_Kh[(base + sb + gr + 8) * 16 + kk0] = __floats2half2_rn(acc[8 + nt][2], acc[8 + nt][3]);
    }

    const int s0 = (blockIdx.x * 64) & 2047;
    const int bb = (blockIdx.x * 64) >> 11;
#pragma unroll
    for (int q = 0; q < 4; q++) {
        const int idx = q * 128 + tid;
        const int c   = idx >> 3;
        const int j   = idx & 7;
        const int h   = c >> 4;
        const int kk  = c & 15;
        __half2 p0 = __halves2half2(stage_v[(8*j+0)*66+c], stage_v[(8*j+1)*66+c]);
        __half2 p1 = __halves2half2(stage_v[(8*j+2)*66+c], stage_v[(8*j+3)*66+c]);
        __half2 p2 = __halves2half2(stage_v[(8*j+4)*66+c], stage_v[(8*j+5)*66+c]);
        __half2 p3 = __halves2half2(stage_v[(8*j+6)*66+c], stage_v[(8*j+7)*66+c]);
        uint4 u;
        u.x = *(unsigned*)&p0; u.y = *(unsigned*)&p1;
        u.z = *(unsigned*)&p2; u.w = *(unsigned*)&p3;
        *(uint4*)&g_Vt[((size_t)(bb * 4 + h) * 16 + kk) * 2048 + s0 + 8 * j] = u;
    }
}

// =====================================================================
// Kernel 2: fp16 tensor-core flash attention (no-max softmax).
// 16 q-rows per warp, 64 per block, grid (32 bh, 32 q-slabs) = 1024 blocks.
// =====================================================================
__global__ void __launch_bounds__(128) attn_kernel()
{
    __shared__ __align__(16) __half Ksh[2][BK][24];
    __shared__ __align__(16) __half Vts[2][24][72];

    const int bh   = blockIdx.x;
    const int tid  = threadIdx.x;
    const int warp = tid >> 5;
    const int lane = tid & 31;
    const int gr   = lane >> 2;
    const int gc   = lane & 3;
    const int qrow0 = blockIdx.y * 64 + warp * 16;

    // constant rows 16..23 of Vt tiles: dim16 = ones (row-sum column), rest 0
    for (int i = tid; i < 2 * 8 * 72; i += 128) {
        int bufi = i / (8 * 72);
        int rem  = i % (8 * 72);
        int r = rem / 72, cc = rem % 72;
        Vts[bufi][16 + r][cc] = __float2half(r == 0 ? 1.0f : 0.0f);
    }

    // Q fragment (one 16-row tile, held for whole kernel)
    const __half* Qbh = g_Qh + (size_t)bh * SS * HEADD;
    unsigned qa[4];
    {
        const __half* r0 = Qbh + (size_t)(qrow0 + gr) * HEADD;
        qa[0] = *(const unsigned*)(r0 + 2 * gc);
        qa[1] = *(const unsigned*)(r0 + 8 * HEADD + 2 * gc);
        qa[2] = *(const unsigned*)(r0 + 2 * gc + 8);
        qa[3] = *(const unsigned*)(r0 + 8 * HEADD + 2 * gc + 8);
    }

    const __half* Kbh = g_Kh + (size_t)bh * SS * HEADD;
    const __half* Vbh = g_Vt + (size_t)bh * HEADD * SS;

    const int kr = tid >> 1, ko = (tid & 1) * 8;
    const int vd = tid >> 3, vo = (tid & 7) * 8;

    float4 nk = *(const float4*)(Kbh + (size_t)kr * HEADD + ko);
    float4 nv = *(const float4*)(Vbh + (size_t)vd * SS + vo);
    *(float4*)&Ksh[0][kr][ko] = nk;
    *(float4*)&Vts[0][vd][vo] = nv;
    __syncthreads();

    float O[3][4] = {};       // [nv-tile][frag]; nv=2 column 16 carries l
    unsigned P[8][2];

    for (int c = 0; c < NCH; c++) {
        const int buf = c & 1;
        if (c + 1 < NCH) {
            nk = *(const float4*)(Kbh + (size_t)((c + 1) * BK + kr) * HEADD + ko);
            nv = *(const float4*)(Vbh + (size_t)vd * SS + (c + 1) * BK + vo);
        }

        // ---- S = Q @ K^T, then P = exp2(S) packed fp16 ----
#pragma unroll
        for (int nt = 0; nt < 8; nt++) {
            unsigned b0 = *(const unsigned*)&Ksh[buf][nt * 8 + gr][2 * gc];
            unsigned b1 = *(const unsigned*)&Ksh[buf][nt * 8 + gr][2 * gc + 8];
            float s[4] = {0.f, 0.f, 0.f, 0.f};
            mma_16816(s, qa, b0, b1);
            __half2 p0 = h2exp2(__floats2half2_rn(s[0], s[1]));
            __half2 p1 = h2exp2(__floats2half2_rn(s[2], s[3]));
            P[nt][0] = *(unsigned*)&p0; P[nt][1] = *(unsigned*)&p1;
        }

        // ---- O += P @ Vt (nv=2 tile accumulates l via ones column) ----
#pragma unroll
        for (int kt = 0; kt < 4; kt++) {
            unsigned a0[4] = { P[2*kt][0], P[2*kt][1],
                               P[2*kt+1][0], P[2*kt+1][1] };
#pragma unroll
            for (int nvt = 0; nvt < 3; nvt++) {
                unsigned b0 = *(const unsigned*)&Vts[buf][nvt * 8 + gr][kt * 16 + 2 * gc];
                unsigned b1 = *(const unsigned*)&Vts[buf][nvt * 8 + gr][kt * 16 + 2 * gc + 8];
                mma_16816(O[nvt], a0, b0, b1);
            }
        }

        __syncthreads();
        if (c + 1 < NCH) {
            *(float4*)&Ksh[buf ^ 1][kr][ko] = nk;
            *(float4*)&Vts[buf ^ 1][vd][vo] = nv;
        }
        __syncthreads();
    }

    // ---- epilogue: normalize by l (column 16) and store ----
    const int b = bh >> 2, h = bh & 3;
    const int srclane = lane & ~3;   // gc==0 lane of this quad holds col 16
    float l_lo = __shfl_sync(0xffffffffu, O[2][0], srclane);
    float l_hi = __shfl_sync(0xffffffffu, O[2][2], srclane);
    const float inv_lo = 1.f / l_lo;
    const float inv_hi = 1.f / l_hi;
    const int r_lo = qrow0 + gr;
    const int r_hi = r_lo + 8;
#pragma unroll
    for (int nvt = 0; nvt < 2; nvt++) {
        float2 vlo = make_float2(O[nvt][0] * inv_lo, O[nvt][1] * inv_lo);
        float2 vhi = make_float2(O[nvt][2] * inv_hi, O[nvt][3] * inv_hi);
        *(float2*)&g_heads[((size_t)(b * SS) + r_lo) * EMB + h * HEADD + nvt * 8 + 2 * gc] = vlo;
        *(float2*)&g_heads[((size_t)(b * SS) + r_hi) * EMB + h * HEADD + nvt * 8 + 2 * gc] = vhi;
    }
}

// =====================================================================
// Kernel 3: post block on tensor cores. B-frags direct from L1/L2.
// =====================================================================
__global__ void __launch_bounds__(128) post_kernel(
    const float* __restrict__ data,
    const float* __restrict__ bo,
    const float* __restrict__ g1,  const float* __restrict__ bl1,
    const float* __restrict__ b1,  const float* __restrict__ b2,
    const float* __restrict__ g2,  const float* __restrict__ bl2,
    float* __restrict__ out)
{
    const int tid  = threadIdx.x;
    const int warp = tid >> 5;
    const int lane = tid & 31;
    const int gr   = lane >> 2;
    const int gc   = lane & 3;

    const int tile = blockIdx.x * 4 + warp;
    const int tok0 = tile * 16;
    const float* rowL = data + (size_t)(tok0 + gr) * 64;
    const float* rowH = rowL + 8 * 64;

    // A fragments from g_heads
    unsigned a[4][4];
#pragma unroll
    for (int kt = 0; kt < 4; kt++) {
        const float* r0 = g_heads + (size_t)(tok0 + gr) * 64 + kt * 16 + 2 * gc;
        const float* r8 = r0 + 8 * 64;
        float2 x0 = *(const float2*)r0;
        float2 x8 = *(const float2*)r8;
        float2 y0 = *(const float2*)(r0 + 8);
        float2 y8 = *(const float2*)(r8 + 8);
        a[kt][0] = packh2(x0.x, x0.y); a[kt][1] = packh2(x8.x, x8.y);
        a[kt][2] = packh2(y0.x, y0.y); a[kt][3] = packh2(y8.x, y8.y);
    }

    // ---- GEMM1: heads @ Wo ----
    float acc[8][4] = {};
#pragma unroll
    for (int nt = 0; nt < 8; nt++)
#pragma unroll
        for (int kt = 0; kt < 4; kt++) {
            const __half* base = &g_Wpost[(nt * 8 + gr) * 72 + kt * 16 + 2 * gc];
            mma_16816(acc[nt], a[kt], *(const unsigned*)base, *(const unsigned*)(base + 8));
        }

    // ---- + residual + bo, LN1 ----
    float x1[8][4];
    float sl = 0.f, sh = 0.f;
#pragma unroll
    for (int nt = 0; nt < 8; nt++) {
        const int col = nt * 8 + 2 * gc;
        float2 dl = *(const float2*)(rowL + col);
        float2 dh = *(const float2*)(rowH + col);
        float2 bb = *(const float2*)(bo + col);
        x1[nt][0] = acc[nt][0] + dl.x + bb.x;
        x1[nt][1] = acc[nt][1] + dl.y + bb.y;
        x1[nt][2] = acc[nt][2] + dh.x + bb.x;
        x1[nt][3] = acc[nt][3] + dh.y + bb.y;
        sl += x1[nt][0] + x1[nt][1];
        sh += x1[nt][2] + x1[nt][3];
    }
    sl += __shfl_xor_sync(0xffffffffu, sl, 1); sl += __shfl_xor_sync(0xffffffffu, sl, 2);
    sh += __shfl_xor_sync(0xffffffffu, sh, 1); sh += __shfl_xor_sync(0xffffffffu, sh, 2);
    float ml = sl * (1.f / 64.f), mh = sh * (1.f / 64.f);
    float vl = 0.f, vh = 0.f;
#pragma unroll
    for (int nt = 0; nt < 8; nt++) {
        x1[nt][0] -= ml; x1[nt][1] -= ml; x1[nt][2] -= mh; x1[nt][3] -= mh;
        vl += x1[nt][0]*x1[nt][0] + x1[nt][1]*x1[nt][1];
        vh += x1[nt][2]*x1[nt][2] + x1[nt][3]*x1[nt][3];
    }
    vl += __shfl_xor_sync(0xffffffffu, vl, 1); vl += __shfl_xor_sync(0xffffffffu, vl, 2);
    vh += __shfl_xor_sync(0xffffffffu, vh, 1); vh += __shfl_xor_sync(0xffffffffu, vh, 2);
    float il = rsqrtf(vl * (1.f / 64.f) + EPS);
    float ih = rsqrtf(vh * (1.f / 64.f) + EPS);
#pragma unroll
    for (int nt = 0; nt < 8; nt++) {
        const int col = nt * 8 + 2 * gc;
        float2 gg = *(const float2*)(g1 + col);
        float2 ee = *(const float2*)(bl1 + col);
        x1[nt][0] = x1[nt][0] * il * gg.x + ee.x;
        x1[nt][1] = x1[nt][1] * il * gg.y + ee.y;
        x1[nt][2] = x1[nt][2] * ih * gg.x + ee.x;
        x1[nt][3] = x1[nt][3] * ih * gg.y + ee.y;
    }

    // ---- GEMM2: x1 @ W1 (C-frag -> A-frag, no shuffles) ----
#pragma unroll
    for (int kt = 0; kt < 4; kt++) {
        a[kt][0] = packh2(x1[2*kt][0],   x1[2*kt][1]);
        a[kt][1] = packh2(x1[2*kt][2],   x1[2*kt][3]);
        a[kt][2] = packh2(x1[2*kt+1][0], x1[2*kt+1][1]);
        a[kt][3] = packh2(x1[2*kt+1][2], x1[2*kt+1][3]);
    }
    float acc2[8][4] = {};
#pragma unroll
    for (int nt = 0; nt < 8; nt++)
#pragma unroll
        for (int kt = 0; kt < 4; kt++) {
            const __half* base = &g_Wpost[(64 + nt * 8 + gr) * 72 + kt * 16 + 2 * gc];
            mma_16816(acc2[nt], a[kt], *(const unsigned*)base, *(const unsigned*)(base + 8));
        }

    // relu(+b1) -> A fragments
#pragma unroll
    for (int nt = 0; nt < 8; nt++) {
        const int col = nt * 8 + 2 * gc;
        float2 bb = *(const float2*)(b1 + col);
        acc2[nt][0] = fmaxf(acc2[nt][0] + bb.x, 0.f);
        acc2[nt][1] = fmaxf(acc2[nt][1] + bb.y, 0.f);
        acc2[nt][2] = fmaxf(acc2[nt][2] + bb.x, 0.f);
        acc2[nt][3] = fmaxf(acc2[nt][3] + bb.y, 0.f);
    }
#pragma unroll
    for (int kt = 0; kt < 4; kt++) {
        a[kt][0] = packh2(acc2[2*kt][0],   acc2[2*kt][1]);
        a[kt][1] = packh2(acc2[2*kt][2],   acc2[2*kt][3]);
        a[kt][2] = packh2(acc2[2*kt+1][0], acc2[2*kt+1][1]);
        a[kt][3] = packh2(acc2[2*kt+1][2], acc2[2*kt+1][3]);
    }

    // ---- GEMM3: h @ W2 ----
    float acc3[8][4] = {};
#pragma unroll
    for (int nt = 0; nt < 8; nt++)
#pragma unroll
        for (int kt = 0; kt < 4; kt++) {
            const __half* base = &g_Wpost[(128 + nt * 8 + gr) * 72 + kt * 16 + 2 * gc];
            mma_16816(acc3[nt], a[kt], *(const unsigned*)base, *(const unsigned*)(base + 8));
        }

    // ---- + b2 + x1, LN2, store ----
    sl = 0.f; sh = 0.f;
#pragma unroll
    for (int nt = 0; nt < 8; nt++) {
        const int col = nt * 8 + 2 * gc;
        float2 bb = *(const float2*)(b2 + col);
        acc3[nt][0] += bb.x + x1[nt][0];
        acc3[nt][1] += bb.y + x1[nt][1];
        acc3[nt][2] += bb.x + x1[nt][2];
        acc3[nt][3] += bb.y + x1[nt][3];
        sl += acc3[nt][0] + acc3[nt][1];
        sh += acc3[nt][2] + acc3[nt][3];
    }
    sl += __shfl_xor_sync(0xffffffffu, sl, 1); sl += __shfl_xor_sync(0xffffffffu, sl, 2);
    sh += __shfl_xor_sync(0xffffffffu, sh, 1); sh += __shfl_xor_sync(0xffffffffu, sh, 2);
    ml = sl * (1.f / 64.f); mh = sh * (1.f / 64.f);
    vl = 0.f; vh = 0.f;
#pragma unroll
    for (int nt = 0; nt < 8; nt++) {
        acc3[nt][0] -= ml; acc3[nt][1] -= ml; acc3[nt][2] -= mh; acc3[nt][3] -= mh;
        vl += acc3[nt][0]*acc3[nt][0] + acc3[nt][1]*acc3[nt][1];
        vh += acc3[nt][2]*acc3[nt][2] + acc3[nt][3]*acc3[nt][3];
    }
    vl += __shfl_xor_sync(0xffffffffu, vl, 1); vl += __shfl_xor_sync(0xffffffffu, vl, 2);
    vh += __shfl_xor_sync(0xffffffffu, vh, 1); vh += __shfl_xor_sync(0xffffffffu, vh, 2);
    il = rsqrtf(vl * (1.f / 64.f) + EPS);
    ih = rsqrtf(vh * (1.f / 64.f) + EPS);

    float* outL = out + (size_t)(tok0 + gr) * 64;
    float* outH = outL + 8 * 64;
#pragma unroll
    for (int nt = 0; nt < 8; nt++) {
        const int col = nt * 8 + 2 * gc;
        float2 gg = *(const float2*)(g2 + col);
        float2 ee = *(const float2*)(bl2 + col);
        *(float2*)(outL + col) = make_float2(acc3[nt][0] * il * gg.x + ee.x,
                                             acc3[nt][1] * il * gg.y + ee.y);
        *(float2*)(outH + col) = make_float2(acc3[nt][2] * ih * gg.x + ee.x,
                                             acc3[nt][3] * ih * gg.y + ee.y);
    }
}

// =====================================================================
extern "C" void kernel_launch(void* const* d_in, const int* in_sizes, int n_in,
                              void* d_out, int out_size)
{
    const float* data  = (const float*)d_in[0];
    const float* Wq    = (const float*)d_in[1];
    const float* Wk    = (const float*)d_in[2];
    const float* Wv    = (const float*)d_in[3];
    const float* Wo    = (const float*)d_in[4];
    const float* bo    = (const float*)d_in[5];
    const float* ln1_g = (const float*)d_in[6];
    const float* ln1_b = (const float*)d_in[7];
    const float* W1    = (const float*)d_in[8];
    const float* b1    = (const float*)d_in[9];
    const float* W2    = (const float*)d_in[10];
    const float* b2    = (const float*)d_in[11];
    const float* ln2_g = (const float*)d_in[12];
    const float* ln2_b = (const float*)d_in[13];
    float* out = (float*)d_out;

    prep_kernel<<<96, 256>>>(Wq, Wk, Wv, Wo, W1, W2);
    qkv_kernel<<<256, 128>>>(data);
    attn_kernel<<<dim3(NHEAD * BB, SS / 64), 128>>>();
    post_kernel<<<256, 128>>>(data, bo, ln1_g, ln1_b, b1, b2, ln2_g, ln2_b, out);
}